// round 1
// baseline (speedup 1.0000x reference)
#include <cuda_runtime.h>
#include <math.h>

#define D_MODEL 1024
#define NHEAD 8
#define CHEAD 128
#define BATCH 4
#define SEQ 2048
#define ROWS (BATCH*SEQ)   /* 8192 */

// ---------------- scratch (module-static device memory; no runtime allocs) ---
__device__ float g_y  [ROWS * D_MODEL];                 // 32 MB: LN outputs (reused)
__device__ float g_q  [BATCH * NHEAD * SEQ * CHEAD];    // 32 MB
__device__ float g_k  [BATCH * NHEAD * SEQ * CHEAD];    // 32 MB
__device__ float g_v  [BATCH * NHEAD * SEQ * CHEAD];    // 32 MB
__device__ float g_att[ROWS * D_MODEL];                 // 32 MB: attn out + x  (= y2)
__device__ float g_h1 [ROWS * 4 * D_MODEL];             // 128 MB: MLP hidden

// ---------------------------------------------------------------- LayerNorm --
__global__ void __launch_bounds__(256) ln_kernel(const float* __restrict__ in,
                                                 const float* __restrict__ gamma,
                                                 const float* __restrict__ beta,
                                                 float* __restrict__ out) {
    const int row = blockIdx.x;
    const float* p = in + (size_t)row * D_MODEL;
    float s = 0.f, sq = 0.f;
    for (int i = threadIdx.x; i < D_MODEL; i += 256) {
        float v = p[i];
        s += v; sq += v * v;
    }
    #pragma unroll
    for (int o = 16; o; o >>= 1) {
        s  += __shfl_xor_sync(0xffffffffu, s,  o);
        sq += __shfl_xor_sync(0xffffffffu, sq, o);
    }
    __shared__ float ws[8], wq[8];
    int w = threadIdx.x >> 5, l = threadIdx.x & 31;
    if (l == 0) { ws[w] = s; wq[w] = sq; }
    __syncthreads();
    if (threadIdx.x == 0) {
        float ts = 0.f, tq = 0.f;
        #pragma unroll
        for (int i = 0; i < 8; i++) { ts += ws[i]; tq += wq[i]; }
        ws[0] = ts; wq[0] = tq;
    }
    __syncthreads();
    const float mu  = ws[0] * (1.f / D_MODEL);
    const float var = wq[0] * (1.f / D_MODEL) - mu * mu;
    const float rs  = rsqrtf(var + 1e-3f);
    float* po = out + (size_t)row * D_MODEL;
    for (int i = threadIdx.x; i < D_MODEL; i += 256)
        po[i] = (p[i] - mu) * rs * gamma[i] + beta[i];
}

// ------------------------------------------------------------------- SGEMM --
// C[M,N] = A[M,K] @ B[K,N], 128x128 block tile, BK=8, 256 threads, 8x8/thread.
// EPI 0: bias + relu, scatter QKV to g_q/g_k/g_v ([B,H,N,C] contiguous)
// EPI 1: bias + relu -> Cout
// EPI 2: bias + residual(res) -> Cout
template<int EPI>
__global__ void __launch_bounds__(256) sgemm_kernel(const float* __restrict__ A,
                                                    const float* __restrict__ B,
                                                    const float* __restrict__ bias,
                                                    const float* __restrict__ res,
                                                    float* __restrict__ Cout,
                                                    int M, int N, int K) {
    __shared__ float As[8 * 128];
    __shared__ float Bs[8 * 132];

    const int tid = threadIdx.x;
    const int tx = tid & 15, ty = tid >> 4;
    const int bx = blockIdx.x, by = blockIdx.y;

    const int arow = tid >> 1, acol = (tid & 1) * 4;
    const int brow = tid >> 5, bcol = (tid & 31) * 4;

    const float* Ap = A + (size_t)(by * 128 + arow) * K + acol;
    const float* Bp = B + (size_t)brow * N + bx * 128 + bcol;

    float acc[8][8];
    #pragma unroll
    for (int i = 0; i < 8; i++)
        #pragma unroll
        for (int j = 0; j < 8; j++) acc[i][j] = 0.f;

    for (int k0 = 0; k0 < K; k0 += 8) {
        float4 a = *(const float4*)(Ap + k0);
        As[(acol + 0) * 128 + arow] = a.x;
        As[(acol + 1) * 128 + arow] = a.y;
        As[(acol + 2) * 128 + arow] = a.z;
        As[(acol + 3) * 128 + arow] = a.w;
        float4 bv = *(const float4*)(Bp + (size_t)k0 * N);
        *(float4*)&Bs[brow * 132 + bcol] = bv;
        __syncthreads();
        #pragma unroll
        for (int kk = 0; kk < 8; kk++) {
            float ar[8], br[8];
            #pragma unroll
            for (int i = 0; i < 8; i++) ar[i] = As[kk * 128 + ty * 8 + i];
            #pragma unroll
            for (int j = 0; j < 8; j++) br[j] = Bs[kk * 132 + j * 16 + tx];
            #pragma unroll
            for (int i = 0; i < 8; i++)
                #pragma unroll
                for (int j = 0; j < 8; j++) acc[i][j] = fmaf(ar[i], br[j], acc[i][j]);
        }
        __syncthreads();
    }

    #pragma unroll
    for (int i = 0; i < 8; i++) {
        const int row = by * 128 + ty * 8 + i;
        #pragma unroll
        for (int j = 0; j < 8; j++) {
            const int col = bx * 128 + j * 16 + tx;
            float v = acc[i][j] + bias[col];
            if (EPI == 0) {
                v = fmaxf(v, 0.f);
                // col = c*24 + h*3 + i  (einops 'b n (c h i)')
                const int c   = col / 24;
                const int rem = col - c * 24;
                const int hh  = rem / 3;
                const int ii  = rem - hh * 3;
                const int bb  = row >> 11;       // row = b*SEQ + n, SEQ=2048
                const int nn  = row & 2047;
                const size_t dst = (((size_t)bb * NHEAD + hh) * SEQ + nn) * CHEAD + c;
                float* dptr = (ii == 0) ? g_q : (ii == 1) ? g_k : g_v;
                dptr[dst] = v;
            } else if (EPI == 1) {
                Cout[(size_t)row * N + col] = fmaxf(v, 0.f);
            } else {
                Cout[(size_t)row * N + col] = v + res[(size_t)row * N + col];
            }
        }
    }
}

// --------------------------------------------------------------- Attention --
// One CTA per (b, h, 64-query tile); flash-style streaming softmax over K.
// Output fused with residual: g_att = softmax(QK^T*scale) @ V  (+ x).
#define ATTN_SMEM_FLOATS (64*128 + 128*65 + 64*128 + 64*65 + 3*64)
#define ATTN_SMEM_BYTES  (ATTN_SMEM_FLOATS * 4)

__global__ void __launch_bounds__(256) attn_kernel(const float* __restrict__ x,
                                                   float* __restrict__ out) {
    extern __shared__ float sm[];
    float* sQ  = sm;                 // [64][128]
    float* sKt = sQ  + 64 * 128;     // [128][65]  (K transposed, padded)
    float* sV  = sKt + 128 * 65;     // [64][128]
    float* sS  = sV  + 64 * 128;     // [64][65]   (padded)
    float* sM  = sS  + 64 * 65;      // [64]
    float* sL  = sM  + 64;           // [64]
    float* sA  = sL  + 64;           // [64]

    const int qb = blockIdx.x, h = blockIdx.y, b = blockIdx.z;
    const int tid = threadIdx.x;
    const int tx = tid & 15, ty = tid >> 4;

    const size_t bh = ((size_t)b * NHEAD + h) * SEQ;
    const float* Qg = g_q + (bh + qb * 64) * CHEAD;

    for (int idx = tid * 4; idx < 64 * 128; idx += 1024)
        *(float4*)&sQ[idx] = *(const float4*)&Qg[idx];
    if (tid < 64) { sM[tid] = -1e30f; sL[tid] = 0.f; }

    float o[4][8];
    #pragma unroll
    for (int i = 0; i < 4; i++)
        #pragma unroll
        for (int j = 0; j < 8; j++) o[i][j] = 0.f;

    for (int kt = 0; kt < SEQ / 64; kt++) {
        __syncthreads();  // previous tile's sS/sV fully consumed
        const float* Kg = g_k + (bh + (size_t)kt * 64) * CHEAD;
        const float* Vg = g_v + (bh + (size_t)kt * 64) * CHEAD;
        for (int idx = tid; idx < 64 * 128; idx += 256) {
            int r = idx >> 7, c = idx & 127;
            sKt[c * 65 + r] = Kg[idx];
        }
        for (int idx = tid * 4; idx < 64 * 128; idx += 1024)
            *(float4*)&sV[idx] = *(const float4*)&Vg[idx];
        __syncthreads();

        // S = Q @ K^T * scale ; thread covers rows ty*4+i, cols j*16+tx
        float s[4][4];
        #pragma unroll
        for (int i = 0; i < 4; i++)
            #pragma unroll
            for (int j = 0; j < 4; j++) s[i][j] = 0.f;
        for (int c = 0; c < 128; c++) {
            float qr[4], kr[4];
            #pragma unroll
            for (int i = 0; i < 4; i++) qr[i] = sQ[(ty * 4 + i) * 128 + c];
            #pragma unroll
            for (int j = 0; j < 4; j++) kr[j] = sKt[c * 65 + j * 16 + tx];
            #pragma unroll
            for (int i = 0; i < 4; i++)
                #pragma unroll
                for (int j = 0; j < 4; j++) s[i][j] = fmaf(qr[i], kr[j], s[i][j]);
        }
        #pragma unroll
        for (int i = 0; i < 4; i++)
            #pragma unroll
            for (int j = 0; j < 4; j++)
                sS[(ty * 4 + i) * 65 + j * 16 + tx] = s[i][j] * 0.125f;
        __syncthreads();

        // online softmax, one thread per row
        if (tid < 64) {
            float m = sM[tid], mn = m;
            float* rowp = sS + tid * 65;
            #pragma unroll 8
            for (int j = 0; j < 64; j++) mn = fmaxf(mn, rowp[j]);
            const float alpha = __expf(m - mn);
            float l = sL[tid] * alpha;
            #pragma unroll 8
            for (int j = 0; j < 64; j++) {
                float p = __expf(rowp[j] - mn);
                rowp[j] = p; l += p;
            }
            sM[tid] = mn; sL[tid] = l; sA[tid] = alpha;
        }
        __syncthreads();

        // O = O*alpha + P @ V ; thread covers rows ty*4+i, cols j*16+tx
        float al[4];
        #pragma unroll
        for (int i = 0; i < 4; i++) al[i] = sA[ty * 4 + i];
        #pragma unroll
        for (int i = 0; i < 4; i++)
            #pragma unroll
            for (int j = 0; j < 8; j++) o[i][j] *= al[i];
        for (int k = 0; k < 64; k++) {
            float p[4], v[8];
            #pragma unroll
            for (int i = 0; i < 4; i++) p[i] = sS[(ty * 4 + i) * 65 + k];
            #pragma unroll
            for (int j = 0; j < 8; j++) v[j] = sV[k * 128 + j * 16 + tx];
            #pragma unroll
            for (int i = 0; i < 4; i++)
                #pragma unroll
                for (int j = 0; j < 8; j++) o[i][j] = fmaf(p[i], v[j], o[i][j]);
        }
    }

    #pragma unroll
    for (int i = 0; i < 4; i++) {
        const int q = qb * 64 + ty * 4 + i;
        const float inv = 1.f / sL[ty * 4 + i];
        const size_t base = ((size_t)b * SEQ + q) * D_MODEL + h * CHEAD;
        #pragma unroll
        for (int j = 0; j < 8; j++) {
            const int c = j * 16 + tx;
            out[base + c] = o[i][j] * inv + x[base + c];
        }
    }
}

// ------------------------------------------------------------------ launch --
extern "C" void kernel_launch(void* const* d_in, const int* in_sizes, int n_in,
                              void* d_out, int out_size) {
    const float* x    = (const float*)d_in[0];
    const float* ln_g = (const float*)d_in[1];
    const float* ln_b = (const float*)d_in[2];
    const float* w3   = (const float*)d_in[3];
    const float* b3   = (const float*)d_in[4];
    const float* w1   = (const float*)d_in[5];
    const float* b1   = (const float*)d_in[6];
    const float* w2   = (const float*)d_in[7];
    const float* b2   = (const float*)d_in[8];
    float* out = (float*)d_out;

    float *y, *att, *h1;
    cudaGetSymbolAddress((void**)&y,   g_y);
    cudaGetSymbolAddress((void**)&att, g_att);
    cudaGetSymbolAddress((void**)&h1,  g_h1);

    cudaFuncSetAttribute(attn_kernel, cudaFuncAttributeMaxDynamicSharedMemorySize,
                         ATTN_SMEM_BYTES);

    // 1) y = LN(x)
    ln_kernel<<<ROWS, 256>>>(x, ln_g, ln_b, y);
    // 2) qkv = relu(y@w3+b3), scattered to g_q/g_k/g_v
    sgemm_kernel<0><<<dim3(3 * D_MODEL / 128, ROWS / 128), 256>>>(
        y, w3, b3, nullptr, nullptr, ROWS, 3 * D_MODEL, D_MODEL);
    // 3) att = attention(q,k,v) + x
    attn_kernel<<<dim3(SEQ / 64, NHEAD, BATCH), 256, ATTN_SMEM_BYTES>>>(x, att);
    // 4) y = LN(att)
    ln_kernel<<<ROWS, 256>>>(att, ln_g, ln_b, y);
    // 5) h1 = relu(y@w1+b1)
    sgemm_kernel<1><<<dim3(4 * D_MODEL / 128, ROWS / 128), 256>>>(
        y, w1, b1, nullptr, h1, ROWS, 4 * D_MODEL, D_MODEL);
    // 6) out = h1@w2 + b2 + att
    sgemm_kernel<2><<<dim3(D_MODEL / 128, ROWS / 128), 256>>>(
        h1, w2, b2, att, out, ROWS, D_MODEL, 4 * D_MODEL);
}

// round 3
// speedup vs baseline: 1.2635x; 1.2635x over previous
#include <cuda_runtime.h>
#include <mma.h>
#include <math.h>
#include <stdint.h>

using namespace nvcuda;

#define D_MODEL 1024
#define NHEAD 8
#define CHEAD 128
#define BATCH 4
#define SEQ 2048
#define ROWS (BATCH*SEQ)   /* 8192 */

// ---------------- scratch (module-static device memory; no runtime allocs) ---
__device__ float g_y  [ROWS * D_MODEL];
__device__ float g_q  [BATCH * NHEAD * SEQ * CHEAD];
__device__ float g_k  [BATCH * NHEAD * SEQ * CHEAD];
__device__ float g_v  [BATCH * NHEAD * SEQ * CHEAD];
__device__ float g_att[ROWS * D_MODEL];
__device__ float g_h1 [ROWS * 4 * D_MODEL];

// ------------------------------------------------------------ PTX helpers ---
__device__ __forceinline__ uint32_t smem_u32(const void* p) {
    uint32_t r;
    asm("{ .reg .u64 t; cvta.to.shared.u64 t, %1; cvt.u32.u64 %0, t; }"
        : "=r"(r) : "l"(p));
    return r;
}
__device__ __forceinline__ void cp16(uint32_t dst, const float* src) {
    asm volatile("cp.async.ca.shared.global [%0], [%1], 16;\n" :: "r"(dst), "l"(src));
}
__device__ __forceinline__ void cp_commit() {
    asm volatile("cp.async.commit_group;\n" ::: "memory");
}
__device__ __forceinline__ void cp_wait0() {
    asm volatile("cp.async.wait_group 0;\n" ::: "memory");
}

// ---------------------------------------------------------------- LayerNorm --
__global__ void __launch_bounds__(256) ln_kernel(const float* __restrict__ in,
                                                 const float* __restrict__ gamma,
                                                 const float* __restrict__ beta,
                                                 float* __restrict__ out) {
    const int row = blockIdx.x;
    const float* p = in + (size_t)row * D_MODEL;
    float s = 0.f, sq = 0.f;
    for (int i = threadIdx.x; i < D_MODEL; i += 256) {
        float v = p[i];
        s += v; sq += v * v;
    }
    #pragma unroll
    for (int o = 16; o; o >>= 1) {
        s  += __shfl_xor_sync(0xffffffffu, s,  o);
        sq += __shfl_xor_sync(0xffffffffu, sq, o);
    }
    __shared__ float ws[8], wq[8];
    int w = threadIdx.x >> 5, l = threadIdx.x & 31;
    if (l == 0) { ws[w] = s; wq[w] = sq; }
    __syncthreads();
    if (threadIdx.x == 0) {
        float ts = 0.f, tq = 0.f;
        #pragma unroll
        for (int i = 0; i < 8; i++) { ts += ws[i]; tq += wq[i]; }
        ws[0] = ts; wq[0] = tq;
    }
    __syncthreads();
    const float mu  = ws[0] * (1.f / D_MODEL);
    const float var = wq[0] * (1.f / D_MODEL) - mu * mu;
    const float rs  = rsqrtf(var + 1e-3f);
    float* po = out + (size_t)row * D_MODEL;
    for (int i = threadIdx.x; i < D_MODEL; i += 256)
        po[i] = (p[i] - mu) * rs * gamma[i] + beta[i];
}

// ------------------------------------------------------- TF32 tensor GEMM ---
// C[M,N] = A[M,K] @ B[K,N]. CTA tile 128x128, BK=16, 256 threads (8 warps),
// warp tile 32x64 (2x4 wmma 16x16x8 fragments). cp.async double buffering.
// EPI 0: bias+relu, scatter QKV ; EPI 1: bias+relu ; EPI 2: bias+residual.
#define BK 16
#define AST 20   /* As row stride (pad) */
#define BST 132  /* Bs row stride (pad) */

template<int EPI>
__global__ void __launch_bounds__(256) tgemm_kernel(const float* __restrict__ A,
                                                    const float* __restrict__ B,
                                                    const float* __restrict__ bias,
                                                    const float* __restrict__ res,
                                                    float* __restrict__ Cout,
                                                    int M, int N, int K) {
    __shared__ float As[2][128][AST];
    __shared__ float Bs[2][BK][BST];

    const int tid  = threadIdx.x;
    const int wid  = tid >> 5, lane = tid & 31;
    const int wm   = wid & 3;       // warp row block (32 rows each)
    const int wn   = wid >> 2;      // warp col block (64 cols each)
    const int bx = blockIdx.x, by = blockIdx.y;

    const float* Ag = A + (size_t)(by * 128) * K;
    const float* Bg = B + (size_t)bx * 128;

    const int ar0 = tid >> 2,           ac0 = (tid & 3) * 4;
    const int ar1 = (tid + 256) >> 2;
    const int br0 = tid >> 5,           bc0 = (tid & 31) * 4;
    const int br1 = (tid + 256) >> 5;

    // precompute smem dst addresses for both buffers
    uint32_t dA0[2], dA1[2], dB0[2], dB1[2];
    #pragma unroll
    for (int b = 0; b < 2; b++) {
        dA0[b] = smem_u32(&As[b][ar0][ac0]);
        dA1[b] = smem_u32(&As[b][ar1][ac0]);
        dB0[b] = smem_u32(&Bs[b][br0][bc0]);
        dB1[b] = smem_u32(&Bs[b][br1][bc0]);
    }

    wmma::fragment<wmma::accumulator, 16, 16, 8, float> acc[2][4];
    #pragma unroll
    for (int i = 0; i < 2; i++)
        #pragma unroll
        for (int j = 0; j < 4; j++) wmma::fill_fragment(acc[i][j], 0.f);

    // prologue: stage 0
    {
        const int k0 = 0;
        cp16(dA0[0], Ag + (size_t)ar0 * K + k0 + ac0);
        cp16(dA1[0], Ag + (size_t)ar1 * K + k0 + ac0);
        cp16(dB0[0], Bg + (size_t)(k0 + br0) * N + bc0);
        cp16(dB1[0], Bg + (size_t)(k0 + br1) * N + bc0);
        cp_commit();
    }

    const int iters = K / BK;
    for (int it = 0; it < iters; it++) {
        const int buf = it & 1;
        cp_wait0();
        __syncthreads();
        if (it + 1 < iters) {
            const int k0 = (it + 1) * BK;
            const int nb = buf ^ 1;
            cp16(dA0[nb], Ag + (size_t)ar0 * K + k0 + ac0);
            cp16(dA1[nb], Ag + (size_t)ar1 * K + k0 + ac0);
            cp16(dB0[nb], Bg + (size_t)(k0 + br0) * N + bc0);
            cp16(dB1[nb], Bg + (size_t)(k0 + br1) * N + bc0);
            cp_commit();
        }

        #pragma unroll
        for (int kk = 0; kk < 2; kk++) {
            wmma::fragment<wmma::matrix_a, 16, 16, 8, wmma::precision::tf32, wmma::row_major> af[2];
            wmma::fragment<wmma::matrix_b, 16, 16, 8, wmma::precision::tf32, wmma::row_major> bf[4];
            #pragma unroll
            for (int i = 0; i < 2; i++) {
                wmma::load_matrix_sync(af[i], &As[buf][wm * 32 + i * 16][kk * 8], AST);
                #pragma unroll
                for (int t = 0; t < af[i].num_elements; t++)
                    af[i].x[t] = wmma::__float_to_tf32(af[i].x[t]);
            }
            #pragma unroll
            for (int j = 0; j < 4; j++) {
                wmma::load_matrix_sync(bf[j], &Bs[buf][kk * 8][wn * 64 + j * 16], BST);
                #pragma unroll
                for (int t = 0; t < bf[j].num_elements; t++)
                    bf[j].x[t] = wmma::__float_to_tf32(bf[j].x[t]);
            }
            #pragma unroll
            for (int i = 0; i < 2; i++)
                #pragma unroll
                for (int j = 0; j < 4; j++)
                    wmma::mma_sync(acc[i][j], af[i], bf[j], acc[i][j]);
        }
        __syncthreads();
    }

    // ------------- epilogue: stage each 16x16 fragment through smem ---------
    float* stage = &As[0][0][0] + wid * (16 * AST);

    #pragma unroll
    for (int i = 0; i < 2; i++) {
        #pragma unroll
        for (int j = 0; j < 4; j++) {
            wmma::store_matrix_sync(stage, acc[i][j], AST, wmma::mem_row_major);
            __syncwarp();
            #pragma unroll
            for (int t = 0; t < 8; t++) {
                const int e  = lane + 32 * t;        // 0..255
                const int r  = e >> 4, c = e & 15;
                const int row = by * 128 + wm * 32 + i * 16 + r;
                const int col = bx * 128 + wn * 64 + j * 16 + c;
                float v = stage[r * AST + c] + bias[col];
                if (EPI == 0) {
                    v = fmaxf(v, 0.f);
                    const int cc  = col / 24;
                    const int rem = col - cc * 24;
                    const int hh  = rem / 3;
                    const int ii  = rem - hh * 3;
                    const int bb  = row >> 11;
                    const int nn  = row & 2047;
                    const size_t dst = (((size_t)bb * NHEAD + hh) * SEQ + nn) * CHEAD + cc;
                    float* dptr = (ii == 0) ? g_q : (ii == 1) ? g_k : g_v;
                    dptr[dst] = v;
                } else if (EPI == 1) {
                    Cout[(size_t)row * N + col] = fmaxf(v, 0.f);
                } else {
                    Cout[(size_t)row * N + col] = v + res[(size_t)row * N + col];
                }
            }
            __syncwarp();
        }
    }
}

// --------------------------------------------------------------- Attention --
#define ATTN_SMEM_FLOATS (64*128 + 128*65 + 64*128 + 64*65 + 3*64)
#define ATTN_SMEM_BYTES  (ATTN_SMEM_FLOATS * 4)

__global__ void __launch_bounds__(256) attn_kernel(const float* __restrict__ x,
                                                   float* __restrict__ out) {
    extern __shared__ float sm[];
    float* sQ  = sm;
    float* sKt = sQ  + 64 * 128;
    float* sV  = sKt + 128 * 65;
    float* sS  = sV  + 64 * 128;
    float* sM  = sS  + 64 * 65;
    float* sL  = sM  + 64;
    float* sA  = sL  + 64;

    const int qb = blockIdx.x, h = blockIdx.y, b = blockIdx.z;
    const int tid = threadIdx.x;
    const int tx = tid & 15, ty = tid >> 4;

    const size_t bh = ((size_t)b * NHEAD + h) * SEQ;
    const float* Qg = g_q + (bh + qb * 64) * CHEAD;

    for (int idx = tid * 4; idx < 64 * 128; idx += 1024)
        *(float4*)&sQ[idx] = *(const float4*)&Qg[idx];
    if (tid < 64) { sM[tid] = -1e30f; sL[tid] = 0.f; }

    float o[4][8];
    #pragma unroll
    for (int i = 0; i < 4; i++)
        #pragma unroll
        for (int j = 0; j < 8; j++) o[i][j] = 0.f;

    for (int kt = 0; kt < SEQ / 64; kt++) {
        __syncthreads();
        const float* Kg = g_k + (bh + (size_t)kt * 64) * CHEAD;
        const float* Vg = g_v + (bh + (size_t)kt * 64) * CHEAD;
        for (int idx = tid; idx < 64 * 128; idx += 256) {
            int r = idx >> 7, c = idx & 127;
            sKt[c * 65 + r] = Kg[idx];
        }
        for (int idx = tid * 4; idx < 64 * 128; idx += 1024)
            *(float4*)&sV[idx] = *(const float4*)&Vg[idx];
        __syncthreads();

        float s[4][4];
        #pragma unroll
        for (int i = 0; i < 4; i++)
            #pragma unroll
            for (int j = 0; j < 4; j++) s[i][j] = 0.f;
        for (int c = 0; c < 128; c++) {
            float qr[4], kr[4];
            #pragma unroll
            for (int i = 0; i < 4; i++) qr[i] = sQ[(ty * 4 + i) * 128 + c];
            #pragma unroll
            for (int j = 0; j < 4; j++) kr[j] = sKt[c * 65 + j * 16 + tx];
            #pragma unroll
            for (int i = 0; i < 4; i++)
                #pragma unroll
                for (int j = 0; j < 4; j++) s[i][j] = fmaf(qr[i], kr[j], s[i][j]);
        }
        #pragma unroll
        for (int i = 0; i < 4; i++)
            #pragma unroll
            for (int j = 0; j < 4; j++)
                sS[(ty * 4 + i) * 65 + j * 16 + tx] = s[i][j] * 0.125f;
        __syncthreads();

        if (tid < 64) {
            float m = sM[tid], mn = m;
            float* rowp = sS + tid * 65;
            #pragma unroll 8
            for (int j = 0; j < 64; j++) mn = fmaxf(mn, rowp[j]);
            const float alpha = __expf(m - mn);
            float l = sL[tid] * alpha;
            #pragma unroll 8
            for (int j = 0; j < 64; j++) {
                float p = __expf(rowp[j] - mn);
                rowp[j] = p; l += p;
            }
            sM[tid] = mn; sL[tid] = l; sA[tid] = alpha;
        }
        __syncthreads();

        float al[4];
        #pragma unroll
        for (int i = 0; i < 4; i++) al[i] = sA[ty * 4 + i];
        #pragma unroll
        for (int i = 0; i < 4; i++)
            #pragma unroll
            for (int j = 0; j < 8; j++) o[i][j] *= al[i];
        for (int k = 0; k < 64; k++) {
            float p[4], v[8];
            #pragma unroll
            for (int i = 0; i < 4; i++) p[i] = sS[(ty * 4 + i) * 65 + k];
            #pragma unroll
            for (int j = 0; j < 8; j++) v[j] = sV[k * 128 + j * 16 + tx];
            #pragma unroll
            for (int i = 0; i < 4; i++)
                #pragma unroll
                for (int j = 0; j < 8; j++) o[i][j] = fmaf(p[i], v[j], o[i][j]);
        }
    }

    #pragma unroll
    for (int i = 0; i < 4; i++) {
        const int q = qb * 64 + ty * 4 + i;
        const float inv = 1.f / sL[ty * 4 + i];
        const size_t base = ((size_t)b * SEQ + q) * D_MODEL + h * CHEAD;
        #pragma unroll
        for (int j = 0; j < 8; j++) {
            const int c = j * 16 + tx;
            out[base + c] = o[i][j] * inv + x[base + c];
        }
    }
}

// ------------------------------------------------------------------ launch --
extern "C" void kernel_launch(void* const* d_in, const int* in_sizes, int n_in,
                              void* d_out, int out_size) {
    const float* x    = (const float*)d_in[0];
    const float* ln_g = (const float*)d_in[1];
    const float* ln_b = (const float*)d_in[2];
    const float* w3   = (const float*)d_in[3];
    const float* b3   = (const float*)d_in[4];
    const float* w1   = (const float*)d_in[5];
    const float* b1   = (const float*)d_in[6];
    const float* w2   = (const float*)d_in[7];
    const float* b2   = (const float*)d_in[8];
    float* out = (float*)d_out;

    float *y, *att, *h1;
    cudaGetSymbolAddress((void**)&y,   g_y);
    cudaGetSymbolAddress((void**)&att, g_att);
    cudaGetSymbolAddress((void**)&h1,  g_h1);

    cudaFuncSetAttribute(attn_kernel, cudaFuncAttributeMaxDynamicSharedMemorySize,
                         ATTN_SMEM_BYTES);

    // 1) y = LN(x)
    ln_kernel<<<ROWS, 256>>>(x, ln_g, ln_b, y);
    // 2) qkv = relu(y@w3+b3) -> scattered q/k/v
    tgemm_kernel<0><<<dim3(3 * D_MODEL / 128, ROWS / 128), 256>>>(
        y, w3, b3, nullptr, nullptr, ROWS, 3 * D_MODEL, D_MODEL);
    // 3) att = attention(q,k,v) + x
    attn_kernel<<<dim3(SEQ / 64, NHEAD, BATCH), 256, ATTN_SMEM_BYTES>>>(x, att);
    // 4) y = LN(att)
    ln_kernel<<<ROWS, 256>>>(att, ln_g, ln_b, y);
    // 5) h1 = relu(y@w1+b1)
    tgemm_kernel<1><<<dim3(4 * D_MODEL / 128, ROWS / 128), 256>>>(
        y, w1, b1, nullptr, h1, ROWS, 4 * D_MODEL, D_MODEL);
    // 6) out = h1@w2 + b2 + att
    tgemm_kernel<2><<<dim3(D_MODEL / 128, ROWS / 128), 256>>>(
        h1, w2, b2, att, out, ROWS, D_MODEL, 4 * D_MODEL);
}

// round 5
// speedup vs baseline: 1.6515x; 1.3071x over previous
#include <cuda_runtime.h>
#include <math.h>
#include <stdint.h>

#define D_MODEL 1024
#define NHEAD 8
#define CHEAD 128
#define BATCH 4
#define SEQ 2048
#define ROWS (BATCH*SEQ)   /* 8192 */

// ---------------- scratch (module-static device memory; no runtime allocs) ---
__device__ __align__(128) float g_y  [ROWS * D_MODEL];
__device__ __align__(128) float g_q  [BATCH * NHEAD * SEQ * CHEAD];
__device__ __align__(128) float g_k  [BATCH * NHEAD * SEQ * CHEAD];
__device__ __align__(128) float g_v  [BATCH * NHEAD * SEQ * CHEAD];
__device__ __align__(128) float g_att[ROWS * D_MODEL];
__device__ __align__(128) float g_h1 [ROWS * 4 * D_MODEL];

// ------------------------------------------------------------ PTX helpers ---
__device__ __forceinline__ uint32_t smem_u32(const void* p) {
    uint32_t r;
    asm("{ .reg .u64 t; cvta.to.shared.u64 t, %1; cvt.u32.u64 %0, t; }"
        : "=r"(r) : "l"(p));
    return r;
}
__device__ __forceinline__ void cp16(uint32_t dst, const float* src) {
    asm volatile("cp.async.ca.shared.global [%0], [%1], 16;\n" :: "r"(dst), "l"(src));
}
__device__ __forceinline__ void cp_commit() {
    asm volatile("cp.async.commit_group;\n" ::: "memory");
}
__device__ __forceinline__ void cp_wait1() {
    asm volatile("cp.async.wait_group 1;\n" ::: "memory");
}
__device__ __forceinline__ void cp_wait0() {
    asm volatile("cp.async.wait_group 0;\n" ::: "memory");
}
// D += A*B, tf32 m16n8k8, A row-major frag (4 regs), B col-major frag (2 regs)
__device__ __forceinline__ void mma8(float* c, const float* a, const float* b) {
    asm volatile(
        "mma.sync.aligned.m16n8k8.row.col.f32.tf32.tf32.f32 "
        "{%0,%1,%2,%3}, {%4,%5,%6,%7}, {%8,%9}, {%0,%1,%2,%3};"
        : "+f"(c[0]), "+f"(c[1]), "+f"(c[2]), "+f"(c[3])
        : "r"(__float_as_uint(a[0])), "r"(__float_as_uint(a[1])),
          "r"(__float_as_uint(a[2])), "r"(__float_as_uint(a[3])),
          "r"(__float_as_uint(b[0])), "r"(__float_as_uint(b[1])));
}

// ---------------------------------------------------------------- LayerNorm --
__global__ void __launch_bounds__(256) ln_kernel(const float* __restrict__ in,
                                                 const float* __restrict__ gamma,
                                                 const float* __restrict__ beta,
                                                 float* __restrict__ out) {
    const int row = blockIdx.x;
    const float* p = in + (size_t)row * D_MODEL;
    float s = 0.f, sq = 0.f;
    for (int i = threadIdx.x; i < D_MODEL; i += 256) {
        float v = p[i];
        s += v; sq += v * v;
    }
    #pragma unroll
    for (int o = 16; o; o >>= 1) {
        s  += __shfl_xor_sync(0xffffffffu, s,  o);
        sq += __shfl_xor_sync(0xffffffffu, sq, o);
    }
    __shared__ float ws[8], wq[8];
    int w = threadIdx.x >> 5, l = threadIdx.x & 31;
    if (l == 0) { ws[w] = s; wq[w] = sq; }
    __syncthreads();
    if (threadIdx.x == 0) {
        float ts = 0.f, tq = 0.f;
        #pragma unroll
        for (int i = 0; i < 8; i++) { ts += ws[i]; tq += wq[i]; }
        ws[0] = ts; wq[0] = tq;
    }
    __syncthreads();
    const float mu  = ws[0] * (1.f / D_MODEL);
    const float var = wq[0] * (1.f / D_MODEL) - mu * mu;
    const float rs  = rsqrtf(var + 1e-3f);
    float* po = out + (size_t)row * D_MODEL;
    for (int i = threadIdx.x; i < D_MODEL; i += 256)
        po[i] = (p[i] - mu) * rs * gamma[i] + beta[i];
}

// ------------------------------------------------ TF32 mma.sync GEMM --------
// C[M,N] = A[M,K] @ B[K,N] (B in natural [K][N] layout).
// CTA 128x128, BK=32, 256 threads / 8 warps, warp tile 64x32.
// smem: As [2][128][36] (m-major), Bs [2][32][136] (k-major). cp.async 2-stage.
#define AST 36
#define BST 136
#define AS_FLOATS (128*AST)          /* 4608 */
#define BS_FLOATS (32*BST)           /* 4352 */
#define GEMM_SMEM_BYTES ((2*AS_FLOATS + 2*BS_FLOATS) * 4)   /* 71680 */

__device__ __forceinline__ void g_load_stage(const float* __restrict__ Ag,
                                             const float* __restrict__ Bg,
                                             int K, int N,
                                             uint32_t aBase, uint32_t bBase,
                                             int k0, int tid) {
    #pragma unroll
    for (int p = 0; p < 4; p++) {
        const int id = p * 256 + tid;            // 0..1023
        // A chunk: m = id>>3, kc = id&7 (16B each)
        const int am = id >> 3, akc = id & 7;
        cp16(aBase + (am * AST + akc * 4) * 4, Ag + (size_t)am * K + k0 + akc * 4);
        // B chunk: kr = id>>5, nc = id&31
        const int bk = id >> 5, bnc = id & 31;
        cp16(bBase + (bk * BST + bnc * 4) * 4, Bg + (size_t)(k0 + bk) * N + bnc * 4);
    }
    cp_commit();
}

// EPI 0: bias+relu+QKV scatter ; EPI 1: bias+relu ; EPI 2: bias+residual.
template<int EPI>
__global__ void __launch_bounds__(256, 2) mgemm_kernel(const float* __restrict__ A,
                                                       const float* __restrict__ B,
                                                       const float* __restrict__ bias,
                                                       const float* __restrict__ res,
                                                       float* __restrict__ Cout,
                                                       int M, int N, int K) {
    extern __shared__ float sm[];
    float* As[2] = { sm, sm + AS_FLOATS };
    float* Bs[2] = { sm + 2 * AS_FLOATS, sm + 2 * AS_FLOATS + BS_FLOATS };

    const int tid = threadIdx.x;
    const int wid = tid >> 5, lane = tid & 31;
    const int wm = wid & 1, wn = wid >> 1;       // 2 x 4 warp grid
    const int lq = lane >> 2, lr = lane & 3;     // lane/4, lane%4
    const int bx = blockIdx.x, by = blockIdx.y;

    const float* Ag = A + (size_t)(by * 128) * K;
    const float* Bg = B + (size_t)bx * 128;

    const uint32_t aBase[2] = { smem_u32(As[0]), smem_u32(As[1]) };
    const uint32_t bBase[2] = { smem_u32(Bs[0]), smem_u32(Bs[1]) };

    float acc[4][4][4];
    #pragma unroll
    for (int f = 0; f < 4; f++)
        #pragma unroll
        for (int g = 0; g < 4; g++)
            #pragma unroll
            for (int e = 0; e < 4; e++) acc[f][g][e] = 0.f;

    const int iters = K >> 5;
    g_load_stage(Ag, Bg, K, N, aBase[0], bBase[0], 0, tid);
    g_load_stage(Ag, Bg, K, N, aBase[1], bBase[1], 32, tid);

    for (int it = 0; it < iters; it++) {
        const int buf = it & 1;
        if (it + 1 < iters) cp_wait1(); else cp_wait0();
        __syncthreads();

        const float* Asb = As[buf];
        const float* Bsb = Bs[buf];
        #pragma unroll
        for (int kk = 0; kk < 4; kk++) {
            float a[4][4], b[4][2];
            #pragma unroll
            for (int f = 0; f < 4; f++) {
                const int r0 = wm * 64 + f * 16 + lq;
                const int c0 = kk * 8 + lr;
                a[f][0] = Asb[r0 * AST + c0];
                a[f][1] = Asb[(r0 + 8) * AST + c0];
                a[f][2] = Asb[r0 * AST + c0 + 4];
                a[f][3] = Asb[(r0 + 8) * AST + c0 + 4];
            }
            #pragma unroll
            for (int g = 0; g < 4; g++) {
                const int n0 = wn * 32 + g * 8 + lq;
                const int k0 = kk * 8 + lr;
                b[g][0] = Bsb[k0 * BST + n0];
                b[g][1] = Bsb[(k0 + 4) * BST + n0];
            }
            #pragma unroll
            for (int f = 0; f < 4; f++)
                #pragma unroll
                for (int g = 0; g < 4; g++)
                    mma8(acc[f][g], a[f], b[g]);
        }
        __syncthreads();
        if (it + 2 < iters)
            g_load_stage(Ag, Bg, K, N, aBase[buf], bBase[buf], (it + 2) << 5, tid);
    }

    // ------------------------------ epilogue --------------------------------
    #pragma unroll
    for (int f = 0; f < 4; f++) {
        #pragma unroll
        for (int g = 0; g < 4; g++) {
            const int row0 = by * 128 + wm * 64 + f * 16 + lq;
            const int col0 = bx * 128 + wn * 32 + g * 8 + lr * 2;
            #pragma unroll
            for (int h = 0; h < 2; h++) {          // h=0: rows row0, h=1: row0+8
                const int row = row0 + h * 8;
                float v0 = acc[f][g][h * 2 + 0] + bias[col0];
                float v1 = acc[f][g][h * 2 + 1] + bias[col0 + 1];
                if (EPI == 0) {
                    v0 = fmaxf(v0, 0.f); v1 = fmaxf(v1, 0.f);
                    #pragma unroll
                    for (int e = 0; e < 2; e++) {
                        const float x = e ? v1 : v0;
                        const int col = col0 + e;
                        const int cc  = col / 24;
                        const int rem = col - cc * 24;
                        const int hh  = rem / 3;
                        const int ii  = rem - hh * 3;
                        const int bb  = row >> 11;
                        const int nn  = row & 2047;
                        const size_t dst = (((size_t)bb * NHEAD + hh) * SEQ + nn) * CHEAD + cc;
                        float* dptr = (ii == 0) ? g_q : (ii == 1) ? g_k : g_v;
                        dptr[dst] = x;
                    }
                } else if (EPI == 1) {
                    float2 o; o.x = fmaxf(v0, 0.f); o.y = fmaxf(v1, 0.f);
                    *(float2*)&Cout[(size_t)row * N + col0] = o;
                } else {
                    const float2 rr = *(const float2*)&res[(size_t)row * N + col0];
                    float2 o; o.x = v0 + rr.x; o.y = v1 + rr.y;
                    *(float2*)&Cout[(size_t)row * N + col0] = o;
                }
            }
        }
    }
}

// --------------------------------------------------------------- Attention --
#define ATTN_SMEM_FLOATS (64*128 + 128*65 + 64*128 + 64*65 + 3*64)
#define ATTN_SMEM_BYTES  (ATTN_SMEM_FLOATS * 4)

__global__ void __launch_bounds__(256) attn_kernel(const float* __restrict__ x,
                                                   float* __restrict__ out) {
    extern __shared__ float smf[];
    float* sQ  = smf;
    float* sKt = sQ  + 64 * 128;
    float* sV  = sKt + 128 * 65;
    float* sS  = sV  + 64 * 128;
    float* sM  = sS  + 64 * 65;
    float* sL  = sM  + 64;
    float* sA  = sL  + 64;

    const int qb = blockIdx.x, h = blockIdx.y, b = blockIdx.z;
    const int tid = threadIdx.x;
    const int tx = tid & 15, ty = tid >> 4;

    const size_t bh = ((size_t)b * NHEAD + h) * SEQ;
    const float* Qg = g_q + (bh + qb * 64) * CHEAD;

    for (int idx = tid * 4; idx < 64 * 128; idx += 1024)
        *(float4*)&sQ[idx] = *(const float4*)&Qg[idx];
    if (tid < 64) { sM[tid] = -1e30f; sL[tid] = 0.f; }

    float o[4][8];
    #pragma unroll
    for (int i = 0; i < 4; i++)
        #pragma unroll
        for (int j = 0; j < 8; j++) o[i][j] = 0.f;

    for (int kt = 0; kt < SEQ / 64; kt++) {
        __syncthreads();
        const float* Kg = g_k + (bh + (size_t)kt * 64) * CHEAD;
        const float* Vg = g_v + (bh + (size_t)kt * 64) * CHEAD;
        for (int idx = tid; idx < 64 * 128; idx += 256) {
            int r = idx >> 7, c = idx & 127;
            sKt[c * 65 + r] = Kg[idx];
        }
        for (int idx = tid * 4; idx < 64 * 128; idx += 1024)
            *(float4*)&sV[idx] = *(const float4*)&Vg[idx];
        __syncthreads();

        float s[4][4];
        #pragma unroll
        for (int i = 0; i < 4; i++)
            #pragma unroll
            for (int j = 0; j < 4; j++) s[i][j] = 0.f;
        for (int c = 0; c < 128; c++) {
            float qr[4], kr[4];
            #pragma unroll
            for (int i = 0; i < 4; i++) qr[i] = sQ[(ty * 4 + i) * 128 + c];
            #pragma unroll
            for (int j = 0; j < 4; j++) kr[j] = sKt[c * 65 + j * 16 + tx];
            #pragma unroll
            for (int i = 0; i < 4; i++)
                #pragma unroll
                for (int j = 0; j < 4; j++) s[i][j] = fmaf(qr[i], kr[j], s[i][j]);
        }
        #pragma unroll
        for (int i = 0; i < 4; i++)
            #pragma unroll
            for (int j = 0; j < 4; j++)
                sS[(ty * 4 + i) * 65 + j * 16 + tx] = s[i][j] * 0.125f;
        __syncthreads();

        if (tid < 64) {
            float m = sM[tid], mn = m;
            float* rowp = sS + tid * 65;
            #pragma unroll 8
            for (int j = 0; j < 64; j++) mn = fmaxf(mn, rowp[j]);
            const float alpha = __expf(m - mn);
            float l = sL[tid] * alpha;
            #pragma unroll 8
            for (int j = 0; j < 64; j++) {
                float p = __expf(rowp[j] - mn);
                rowp[j] = p; l += p;
            }
            sM[tid] = mn; sL[tid] = l; sA[tid] = alpha;
        }
        __syncthreads();

        float al[4];
        #pragma unroll
        for (int i = 0; i < 4; i++) al[i] = sA[ty * 4 + i];
        #pragma unroll
        for (int i = 0; i < 4; i++)
            #pragma unroll
            for (int j = 0; j < 8; j++) o[i][j] *= al[i];
        for (int k = 0; k < 64; k++) {
            float p[4], v[8];
            #pragma unroll
            for (int i = 0; i < 4; i++) p[i] = sS[(ty * 4 + i) * 65 + k];
            #pragma unroll
            for (int j = 0; j < 8; j++) v[j] = sV[k * 128 + j * 16 + tx];
            #pragma unroll
            for (int i = 0; i < 4; i++)
                #pragma unroll
                for (int j = 0; j < 8; j++) o[i][j] = fmaf(p[i], v[j], o[i][j]);
        }
    }

    #pragma unroll
    for (int i = 0; i < 4; i++) {
        const int q = qb * 64 + ty * 4 + i;
        const float inv = 1.f / sL[ty * 4 + i];
        const size_t base = ((size_t)b * SEQ + q) * D_MODEL + h * CHEAD;
        #pragma unroll
        for (int j = 0; j < 8; j++) {
            const int c = j * 16 + tx;
            out[base + c] = o[i][j] * inv + x[base + c];
        }
    }
}

// ------------------------------------------------------------------ launch --
extern "C" void kernel_launch(void* const* d_in, const int* in_sizes, int n_in,
                              void* d_out, int out_size) {
    const float* x    = (const float*)d_in[0];
    const float* ln_g = (const float*)d_in[1];
    const float* ln_b = (const float*)d_in[2];
    const float* w3   = (const float*)d_in[3];
    const float* b3   = (const float*)d_in[4];
    const float* w1   = (const float*)d_in[5];
    const float* b1   = (const float*)d_in[6];
    const float* w2   = (const float*)d_in[7];
    const float* b2   = (const float*)d_in[8];
    float* out = (float*)d_out;

    float *y, *att, *h1;
    cudaGetSymbolAddress((void**)&y,   g_y);
    cudaGetSymbolAddress((void**)&att, g_att);
    cudaGetSymbolAddress((void**)&h1,  g_h1);

    cudaFuncSetAttribute(attn_kernel, cudaFuncAttributeMaxDynamicSharedMemorySize,
                         ATTN_SMEM_BYTES);
    cudaFuncSetAttribute(mgemm_kernel<0>, cudaFuncAttributeMaxDynamicSharedMemorySize,
                         GEMM_SMEM_BYTES);
    cudaFuncSetAttribute(mgemm_kernel<1>, cudaFuncAttributeMaxDynamicSharedMemorySize,
                         GEMM_SMEM_BYTES);
    cudaFuncSetAttribute(mgemm_kernel<2>, cudaFuncAttributeMaxDynamicSharedMemorySize,
                         GEMM_SMEM_BYTES);

    // 1) y = LN(x)
    ln_kernel<<<ROWS, 256>>>(x, ln_g, ln_b, y);
    // 2) qkv = relu(y@w3+b3) -> scattered q/k/v
    mgemm_kernel<0><<<dim3(3072/128, ROWS/128), 256, GEMM_SMEM_BYTES>>>(
        y, w3, b3, nullptr, nullptr, ROWS, 3072, 1024);
    // 3) att = attention(q,k,v) + x
    attn_kernel<<<dim3(SEQ/64, NHEAD, BATCH), 256, ATTN_SMEM_BYTES>>>(x, att);
    // 4) y = LN(att)
    ln_kernel<<<ROWS, 256>>>(att, ln_g, ln_b, y);
    // 5) h1 = relu(y@w1+b1)
    mgemm_kernel<1><<<dim3(4096/128, ROWS/128), 256, GEMM_SMEM_BYTES>>>(
        y, w1, b1, nullptr, h1, ROWS, 4096, 1024);
    // 6) out = h1@w2 + b2 + att
    mgemm_kernel<2><<<dim3(1024/128, ROWS/128), 256, GEMM_SMEM_BYTES>>>(
        h1, w2, b2, att, out, ROWS, 1024, 4096);
}

// round 6
// speedup vs baseline: 2.4444x; 1.4801x over previous
#include <cuda_runtime.h>
#include <math.h>
#include <stdint.h>

#define D_MODEL 1024
#define NHEAD 8
#define CHEAD 128
#define BATCH 4
#define SEQ 2048
#define ROWS (BATCH*SEQ)   /* 8192 */

// ---------------- scratch (module-static device memory; no runtime allocs) ---
__device__ __align__(128) float g_y  [ROWS * D_MODEL];
__device__ __align__(128) float g_q  [BATCH * NHEAD * SEQ * CHEAD];
__device__ __align__(128) float g_k  [BATCH * NHEAD * SEQ * CHEAD];
__device__ __align__(128) float g_v  [BATCH * NHEAD * SEQ * CHEAD];
__device__ __align__(128) float g_att[ROWS * D_MODEL];
__device__ __align__(128) float g_h1 [ROWS * 4 * D_MODEL];
// RN-rounded weight copies
#define WR3_OFF 0
#define WR1_OFF (3072*1024)
#define WR2_OFF (WR1_OFF + 4096*1024)
__device__ __align__(128) float g_wr [WR2_OFF + 4096*1024];

// ------------------------------------------------------------ PTX helpers ---
__device__ __forceinline__ uint32_t smem_u32(const void* p) {
    uint32_t r;
    asm("{ .reg .u64 t; cvta.to.shared.u64 t, %1; cvt.u32.u64 %0, t; }"
        : "=r"(r) : "l"(p));
    return r;
}
__device__ __forceinline__ float tf32r(float x) {
    uint32_t o;
    asm("cvt.rn.tf32.f32 %0, %1;" : "=r"(o) : "f"(x));
    return __uint_as_float(o);
}
__device__ __forceinline__ void cp16(uint32_t dst, const float* src) {
    asm volatile("cp.async.ca.shared.global [%0], [%1], 16;\n" :: "r"(dst), "l"(src));
}
__device__ __forceinline__ void cp_commit() {
    asm volatile("cp.async.commit_group;\n" ::: "memory");
}
__device__ __forceinline__ void cp_wait1() {
    asm volatile("cp.async.wait_group 1;\n" ::: "memory");
}
__device__ __forceinline__ void cp_wait0() {
    asm volatile("cp.async.wait_group 0;\n" ::: "memory");
}
// D += A*B, tf32 m16n8k8, A row-major frag (4 regs), B col-major frag (2 regs)
__device__ __forceinline__ void mma8(float* c, const float* a, const float* b) {
    asm volatile(
        "mma.sync.aligned.m16n8k8.row.col.f32.tf32.tf32.f32 "
        "{%0,%1,%2,%3}, {%4,%5,%6,%7}, {%8,%9}, {%0,%1,%2,%3};"
        : "+f"(c[0]), "+f"(c[1]), "+f"(c[2]), "+f"(c[3])
        : "r"(__float_as_uint(a[0])), "r"(__float_as_uint(a[1])),
          "r"(__float_as_uint(a[2])), "r"(__float_as_uint(a[3])),
          "r"(__float_as_uint(b[0])), "r"(__float_as_uint(b[1])));
}

// -------------------------------------------------------------- RN rounder --
__global__ void __launch_bounds__(256) round_kernel(const float* __restrict__ in,
                                                    float* __restrict__ out, int n4) {
    const int i = blockIdx.x * 256 + threadIdx.x;
    if (i < n4) {
        float4 v = ((const float4*)in)[i];
        v.x = tf32r(v.x); v.y = tf32r(v.y); v.z = tf32r(v.z); v.w = tf32r(v.w);
        ((float4*)out)[i] = v;
    }
}

// ---------------------------------------------------------------- LayerNorm --
__global__ void __launch_bounds__(256) ln_kernel(const float* __restrict__ in,
                                                 const float* __restrict__ gamma,
                                                 const float* __restrict__ beta,
                                                 float* __restrict__ out) {
    const int row = blockIdx.x;
    const float* p = in + (size_t)row * D_MODEL;
    float s = 0.f, sq = 0.f;
    for (int i = threadIdx.x; i < D_MODEL; i += 256) {
        float v = p[i];
        s += v; sq += v * v;
    }
    #pragma unroll
    for (int o = 16; o; o >>= 1) {
        s  += __shfl_xor_sync(0xffffffffu, s,  o);
        sq += __shfl_xor_sync(0xffffffffu, sq, o);
    }
    __shared__ float ws[8], wq[8];
    int w = threadIdx.x >> 5, l = threadIdx.x & 31;
    if (l == 0) { ws[w] = s; wq[w] = sq; }
    __syncthreads();
    if (threadIdx.x == 0) {
        float ts = 0.f, tq = 0.f;
        #pragma unroll
        for (int i = 0; i < 8; i++) { ts += ws[i]; tq += wq[i]; }
        ws[0] = ts; wq[0] = tq;
    }
    __syncthreads();
    const float mu  = ws[0] * (1.f / D_MODEL);
    const float var = wq[0] * (1.f / D_MODEL) - mu * mu;
    const float rs  = rsqrtf(var + 1e-3f);
    float* po = out + (size_t)row * D_MODEL;
    for (int i = threadIdx.x; i < D_MODEL; i += 256)
        po[i] = tf32r((p[i] - mu) * rs * gamma[i] + beta[i]);
}

// ------------------------------------------------ TF32 mma.sync GEMM --------
#define AST 36
#define BST 136
#define AS_FLOATS (128*AST)
#define BS_FLOATS (32*BST)
#define GEMM_SMEM_BYTES ((2*AS_FLOATS + 2*BS_FLOATS) * 4)

__device__ __forceinline__ void g_load_stage(const float* __restrict__ Ag,
                                             const float* __restrict__ Bg,
                                             int K, int N,
                                             uint32_t aBase, uint32_t bBase,
                                             int k0, int tid) {
    #pragma unroll
    for (int p = 0; p < 4; p++) {
        const int id = p * 256 + tid;
        const int am = id >> 3, akc = id & 7;
        cp16(aBase + (am * AST + akc * 4) * 4, Ag + (size_t)am * K + k0 + akc * 4);
        const int bk = id >> 5, bnc = id & 31;
        cp16(bBase + (bk * BST + bnc * 4) * 4, Bg + (size_t)(k0 + bk) * N + bnc * 4);
    }
    cp_commit();
}

// EPI 0: bias+relu+QKV scatter(rounded) ; EPI 1: bias+relu(rounded) ; EPI 2: bias+residual.
template<int EPI>
__global__ void __launch_bounds__(256, 2) mgemm_kernel(const float* __restrict__ A,
                                                       const float* __restrict__ B,
                                                       const float* __restrict__ bias,
                                                       const float* __restrict__ res,
                                                       float* __restrict__ Cout,
                                                       int M, int N, int K) {
    extern __shared__ float sm[];
    float* As[2] = { sm, sm + AS_FLOATS };
    float* Bs[2] = { sm + 2 * AS_FLOATS, sm + 2 * AS_FLOATS + BS_FLOATS };

    const int tid = threadIdx.x;
    const int wid = tid >> 5, lane = tid & 31;
    const int wm = wid & 1, wn = wid >> 1;
    const int lq = lane >> 2, lr = lane & 3;
    const int bx = blockIdx.x, by = blockIdx.y;

    const float* Ag = A + (size_t)(by * 128) * K;
    const float* Bg = B + (size_t)bx * 128;

    const uint32_t aBase[2] = { smem_u32(As[0]), smem_u32(As[1]) };
    const uint32_t bBase[2] = { smem_u32(Bs[0]), smem_u32(Bs[1]) };

    float acc[4][4][4];
    #pragma unroll
    for (int f = 0; f < 4; f++)
        #pragma unroll
        for (int g = 0; g < 4; g++)
            #pragma unroll
            for (int e = 0; e < 4; e++) acc[f][g][e] = 0.f;

    const int iters = K >> 5;
    g_load_stage(Ag, Bg, K, N, aBase[0], bBase[0], 0, tid);
    g_load_stage(Ag, Bg, K, N, aBase[1], bBase[1], 32, tid);

    for (int it = 0; it < iters; it++) {
        const int buf = it & 1;
        if (it + 1 < iters) cp_wait1(); else cp_wait0();
        __syncthreads();

        const float* Asb = As[buf];
        const float* Bsb = Bs[buf];
        #pragma unroll
        for (int kk = 0; kk < 4; kk++) {
            float a[4][4], b[4][2];
            #pragma unroll
            for (int f = 0; f < 4; f++) {
                const int r0 = wm * 64 + f * 16 + lq;
                const int c0 = kk * 8 + lr;
                a[f][0] = Asb[r0 * AST + c0];
                a[f][1] = Asb[(r0 + 8) * AST + c0];
                a[f][2] = Asb[r0 * AST + c0 + 4];
                a[f][3] = Asb[(r0 + 8) * AST + c0 + 4];
            }
            #pragma unroll
            for (int g = 0; g < 4; g++) {
                const int n0 = wn * 32 + g * 8 + lq;
                const int k0 = kk * 8 + lr;
                b[g][0] = Bsb[k0 * BST + n0];
                b[g][1] = Bsb[(k0 + 4) * BST + n0];
            }
            #pragma unroll
            for (int f = 0; f < 4; f++)
                #pragma unroll
                for (int g = 0; g < 4; g++)
                    mma8(acc[f][g], a[f], b[g]);
        }
        __syncthreads();
        if (it + 2 < iters)
            g_load_stage(Ag, Bg, K, N, aBase[buf], bBase[buf], (it + 2) << 5, tid);
    }

    #pragma unroll
    for (int f = 0; f < 4; f++) {
        #pragma unroll
        for (int g = 0; g < 4; g++) {
            const int row0 = by * 128 + wm * 64 + f * 16 + lq;
            const int col0 = bx * 128 + wn * 32 + g * 8 + lr * 2;
            #pragma unroll
            for (int h = 0; h < 2; h++) {
                const int row = row0 + h * 8;
                float v0 = acc[f][g][h * 2 + 0] + bias[col0];
                float v1 = acc[f][g][h * 2 + 1] + bias[col0 + 1];
                if (EPI == 0) {
                    v0 = tf32r(fmaxf(v0, 0.f)); v1 = tf32r(fmaxf(v1, 0.f));
                    #pragma unroll
                    for (int e = 0; e < 2; e++) {
                        const float xv = e ? v1 : v0;
                        const int col = col0 + e;
                        const int cc  = col / 24;
                        const int rem = col - cc * 24;
                        const int hh  = rem / 3;
                        const int ii  = rem - hh * 3;
                        const int bb  = row >> 11;
                        const int nn  = row & 2047;
                        const size_t dst = (((size_t)bb * NHEAD + hh) * SEQ + nn) * CHEAD + cc;
                        float* dptr = (ii == 0) ? g_q : (ii == 1) ? g_k : g_v;
                        dptr[dst] = xv;
                    }
                } else if (EPI == 1) {
                    float2 o; o.x = tf32r(fmaxf(v0, 0.f)); o.y = tf32r(fmaxf(v1, 0.f));
                    *(float2*)&Cout[(size_t)row * N + col0] = o;
                } else {
                    const float2 rr = *(const float2*)&res[(size_t)row * N + col0];
                    float2 o; o.x = v0 + rr.x; o.y = v1 + rr.y;
                    *(float2*)&Cout[(size_t)row * N + col0] = o;
                }
            }
        }
    }
}

// ------------------------------------------------ tensor-core Attention -----
// 64 queries per CTA, 256 threads / 8 warps, K-tiles of 64, online softmax.
#define AQ_ST 132
#define AK_ST 72
#define AV_ST 136
#define AS_ST 68
#define ATTN_SMEM_FLOATS (64*AQ_ST + 128*AK_ST + 64*AV_ST + 64*AS_ST + 3*64)
#define ATTN_SMEM_BYTES  (ATTN_SMEM_FLOATS * 4)

__global__ void __launch_bounds__(256) attn_kernel(const float* __restrict__ x,
                                                   float* __restrict__ out) {
    extern __shared__ float smf[];
    float* sQ  = smf;                   // [64][132]
    float* sKt = sQ  + 64 * AQ_ST;      // [128][72]  (K^T: [c][kv])
    float* sV  = sKt + 128 * AK_ST;     // [64][136]
    float* sS  = sV  + 64 * AV_ST;      // [64][68]
    float* sM  = sS  + 64 * AS_ST;
    float* sL  = sM  + 64;
    float* sA  = sL  + 64;

    const int qb = blockIdx.x, h = blockIdx.y, b = blockIdx.z;
    const int tid = threadIdx.x;
    const int wid = tid >> 5, lane = tid & 31;
    const int lq = lane >> 2, lr = lane & 3;
    const int wm = wid & 3, wn = wid >> 2;   // 4 x 2 warp grid

    const size_t bh = ((size_t)b * NHEAD + h) * SEQ;
    const float* Qg = g_q + (bh + (size_t)qb * 64) * CHEAD;

    for (int idx = tid; idx < 64 * 32; idx += 256) {
        const int r = idx >> 5, c4 = idx & 31;
        *(float4*)&sQ[r * AQ_ST + c4 * 4] = *(const float4*)&Qg[r * 128 + c4 * 4];
    }
    if (tid < 64) { sM[tid] = -1e30f; sL[tid] = 0.f; }

    float oacc[8][4];
    #pragma unroll
    for (int f = 0; f < 8; f++)
        #pragma unroll
        for (int e = 0; e < 4; e++) oacc[f][e] = 0.f;

    for (int kt = 0; kt < SEQ / 64; kt++) {
        __syncthreads();
        const float* Kg = g_k + (bh + (size_t)kt * 64) * CHEAD;
        const float* Vg = g_v + (bh + (size_t)kt * 64) * CHEAD;
        for (int idx = tid; idx < 64 * 128; idx += 256) {
            const int kv = idx >> 7, c = idx & 127;
            sKt[c * AK_ST + kv] = Kg[idx];
        }
        for (int idx = tid; idx < 64 * 32; idx += 256) {
            const int r = idx >> 5, c4 = idx & 31;
            *(float4*)&sV[r * AV_ST + c4 * 4] = *(const float4*)&Vg[r * 128 + c4 * 4];
        }
        __syncthreads();

        // ---- S = Q @ K^T : warp tile 16x32 (wm rows, wn col-half) ----------
        float sc[4][4];
        #pragma unroll
        for (int g = 0; g < 4; g++)
            #pragma unroll
            for (int e = 0; e < 4; e++) sc[g][e] = 0.f;
        #pragma unroll
        for (int kk = 0; kk < 16; kk++) {
            float a[4];
            const int r0 = wm * 16 + lq, c0 = kk * 8 + lr;
            a[0] = sQ[r0 * AQ_ST + c0];
            a[1] = sQ[(r0 + 8) * AQ_ST + c0];
            a[2] = sQ[r0 * AQ_ST + c0 + 4];
            a[3] = sQ[(r0 + 8) * AQ_ST + c0 + 4];
            #pragma unroll
            for (int g = 0; g < 4; g++) {
                const int n0 = wn * 32 + g * 8 + lq;
                const int k0 = kk * 8 + lr;
                float bb[2] = { sKt[k0 * AK_ST + n0], sKt[(k0 + 4) * AK_ST + n0] };
                mma8(sc[g], a, bb);
            }
        }
        {
            const int r0 = wm * 16 + lq;
            #pragma unroll
            for (int g = 0; g < 4; g++) {
                const int c0 = wn * 32 + g * 8 + lr * 2;
                *(float2*)&sS[r0 * AS_ST + c0] =
                    make_float2(sc[g][0] * 0.125f, sc[g][1] * 0.125f);
                *(float2*)&sS[(r0 + 8) * AS_ST + c0] =
                    make_float2(sc[g][2] * 0.125f, sc[g][3] * 0.125f);
            }
        }
        __syncthreads();

        // ---- online softmax: 4 threads per row -----------------------------
        {
            const int row = tid >> 2, seg = (tid & 3) * 16;
            float* rp = sS + row * AS_ST + seg;
            float mx = -1e30f;
            #pragma unroll
            for (int j = 0; j < 16; j++) mx = fmaxf(mx, rp[j]);
            mx = fmaxf(mx, __shfl_xor_sync(0xffffffffu, mx, 1));
            mx = fmaxf(mx, __shfl_xor_sync(0xffffffffu, mx, 2));
            const float mo = sM[row];
            const float mn = fmaxf(mo, mx);
            float l = 0.f;
            #pragma unroll
            for (int j = 0; j < 16; j++) {
                const float p = __expf(rp[j] - mn);
                l += p;
                rp[j] = tf32r(p);
            }
            l += __shfl_xor_sync(0xffffffffu, l, 1);
            l += __shfl_xor_sync(0xffffffffu, l, 2);
            if ((tid & 3) == 0) {
                const float alpha = __expf(mo - mn);
                sA[row] = alpha;
                sL[row] = sL[row] * alpha + l;
                sM[row] = mn;
            }
        }
        __syncthreads();

        // ---- O = O*alpha + P @ V : warp tile 16x64 --------------------------
        const float al0 = sA[wm * 16 + lq];
        const float al1 = sA[wm * 16 + lq + 8];
        #pragma unroll
        for (int f = 0; f < 8; f++) {
            oacc[f][0] *= al0; oacc[f][1] *= al0;
            oacc[f][2] *= al1; oacc[f][3] *= al1;
        }
        #pragma unroll
        for (int kk = 0; kk < 8; kk++) {
            float a[4];
            const int r0 = wm * 16 + lq, c0 = kk * 8 + lr;
            a[0] = sS[r0 * AS_ST + c0];
            a[1] = sS[(r0 + 8) * AS_ST + c0];
            a[2] = sS[r0 * AS_ST + c0 + 4];
            a[3] = sS[(r0 + 8) * AS_ST + c0 + 4];
            #pragma unroll
            for (int f = 0; f < 8; f++) {
                const int n0 = wn * 64 + f * 8 + lq;
                const int k0 = kk * 8 + lr;
                float bb[2] = { sV[k0 * AV_ST + n0], sV[(k0 + 4) * AV_ST + n0] };
                mma8(oacc[f], a, bb);
            }
        }
    }

    // ------------------------------ epilogue --------------------------------
    const int r0 = wm * 16 + lq;
    const float inv0 = 1.f / sL[r0];
    const float inv1 = 1.f / sL[r0 + 8];
    const int q0 = qb * 64 + r0;
    #pragma unroll
    for (int f = 0; f < 8; f++) {
        const int col = wn * 64 + f * 8 + lr * 2;
        const size_t b0 = ((size_t)b * SEQ + q0) * D_MODEL + h * CHEAD + col;
        const size_t b1 = ((size_t)b * SEQ + q0 + 8) * D_MODEL + h * CHEAD + col;
        const float2 x0 = *(const float2*)&x[b0];
        const float2 x1 = *(const float2*)&x[b1];
        float2 o0, o1;
        o0.x = oacc[f][0] * inv0 + x0.x; o0.y = oacc[f][1] * inv0 + x0.y;
        o1.x = oacc[f][2] * inv1 + x1.x; o1.y = oacc[f][3] * inv1 + x1.y;
        *(float2*)&out[b0] = o0;
        *(float2*)&out[b1] = o1;
    }
}

// ------------------------------------------------------------------ launch --
extern "C" void kernel_launch(void* const* d_in, const int* in_sizes, int n_in,
                              void* d_out, int out_size) {
    const float* x    = (const float*)d_in[0];
    const float* ln_g = (const float*)d_in[1];
    const float* ln_b = (const float*)d_in[2];
    const float* w3   = (const float*)d_in[3];
    const float* b3   = (const float*)d_in[4];
    const float* w1   = (const float*)d_in[5];
    const float* b1   = (const float*)d_in[6];
    const float* w2   = (const float*)d_in[7];
    const float* b2   = (const float*)d_in[8];
    float* out = (float*)d_out;

    float *y, *att, *h1, *wr;
    cudaGetSymbolAddress((void**)&y,   g_y);
    cudaGetSymbolAddress((void**)&att, g_att);
    cudaGetSymbolAddress((void**)&h1,  g_h1);
    cudaGetSymbolAddress((void**)&wr,  g_wr);

    cudaFuncSetAttribute(attn_kernel, cudaFuncAttributeMaxDynamicSharedMemorySize,
                         ATTN_SMEM_BYTES);
    cudaFuncSetAttribute(mgemm_kernel<0>, cudaFuncAttributeMaxDynamicSharedMemorySize,
                         GEMM_SMEM_BYTES);
    cudaFuncSetAttribute(mgemm_kernel<1>, cudaFuncAttributeMaxDynamicSharedMemorySize,
                         GEMM_SMEM_BYTES);
    cudaFuncSetAttribute(mgemm_kernel<2>, cudaFuncAttributeMaxDynamicSharedMemorySize,
                         GEMM_SMEM_BYTES);

    // 0) RN-round weights once per launch
    round_kernel<<<(3072*1024/4 + 255)/256, 256>>>(w3, wr + WR3_OFF, 3072*1024/4);
    round_kernel<<<(4096*1024/4 + 255)/256, 256>>>(w1, wr + WR1_OFF, 4096*1024/4);
    round_kernel<<<(4096*1024/4 + 255)/256, 256>>>(w2, wr + WR2_OFF, 4096*1024/4);

    // 1) y = LN(x)  (rounded)
    ln_kernel<<<ROWS, 256>>>(x, ln_g, ln_b, y);
    // 2) qkv = relu(y@w3+b3) -> q/k/v (rounded)
    mgemm_kernel<0><<<dim3(3072/128, ROWS/128), 256, GEMM_SMEM_BYTES>>>(
        y, wr + WR3_OFF, b3, nullptr, nullptr, ROWS, 3072, 1024);
    // 3) att = attention(q,k,v) + x
    attn_kernel<<<dim3(SEQ/64, NHEAD, BATCH), 256, ATTN_SMEM_BYTES>>>(x, att);
    // 4) y = LN(att)  (rounded)
    ln_kernel<<<ROWS, 256>>>(att, ln_g, ln_b, y);
    // 5) h1 = relu(y@w1+b1)  (rounded)
    mgemm_kernel<1><<<dim3(4096/128, ROWS/128), 256, GEMM_SMEM_BYTES>>>(
        y, wr + WR1_OFF, b1, nullptr, h1, ROWS, 4096, 1024);
    // 6) out = h1@w2 + b2 + att
    mgemm_kernel<2><<<dim3(1024/128, ROWS/128), 256, GEMM_SMEM_BYTES>>>(
        h1, wr + WR2_OFF, b2, att, out, ROWS, 1024, 4096);
}

// round 7
// speedup vs baseline: 4.7940x; 1.9612x over previous
#include <cuda_runtime.h>
#include <cuda_fp16.h>
#include <math.h>
#include <stdint.h>

#define D_MODEL 1024
#define NHEAD 8
#define CHEAD 128
#define BATCH 4
#define SEQ 2048
#define ROWS (BATCH*SEQ)   /* 8192 */

// ---------------- scratch (module-static device memory; no runtime allocs) ---
__device__ __align__(128) __half g_yh [ROWS * D_MODEL];              // LN out (half)
__device__ __align__(128) __half g_q  [BATCH * NHEAD * SEQ * CHEAD]; // [b][h][n][c]
__device__ __align__(128) __half g_k  [BATCH * NHEAD * SEQ * CHEAD]; // [b][h][n][c]
__device__ __align__(128) __half g_v  [BATCH * NHEAD * CHEAD * SEQ]; // [b][h][c][n] (pre-transposed)
__device__ __align__(128) float  g_att[ROWS * D_MODEL];              // attn + x (fp32)
__device__ __align__(128) __half g_h1 [ROWS * 4 * D_MODEL];          // MLP hidden (half)
// transposed+converted weights [N][K] half
#define WH3_OFF 0
#define WH1_OFF (3072*1024)
#define WH2_OFF (WH1_OFF + 4096*1024)
__device__ __align__(128) __half g_wh [WH2_OFF + 1024*4096];

// ------------------------------------------------------------ PTX helpers ---
__device__ __forceinline__ uint32_t smem_u32(const void* p) {
    uint32_t r;
    asm("{ .reg .u64 t; cvta.to.shared.u64 t, %1; cvt.u32.u64 %0, t; }"
        : "=r"(r) : "l"(p));
    return r;
}
__device__ __forceinline__ void cp16(uint32_t dst, const void* src) {
    asm volatile("cp.async.ca.shared.global [%0], [%1], 16;\n" :: "r"(dst), "l"(src));
}
__device__ __forceinline__ void cp_commit() {
    asm volatile("cp.async.commit_group;\n" ::: "memory");
}
__device__ __forceinline__ void cp_wait1() {
    asm volatile("cp.async.wait_group 1;\n" ::: "memory");
}
__device__ __forceinline__ void cp_wait0() {
    asm volatile("cp.async.wait_group 0;\n" ::: "memory");
}
// D += A*B, fp16 m16n8k16: A 4 b32 regs (8 halves), B 2 b32 (4 halves), C fp32 x4
__device__ __forceinline__ void mma16(float* c, const uint32_t* a, const uint32_t* b) {
    asm volatile(
        "mma.sync.aligned.m16n8k16.row.col.f32.f16.f16.f32 "
        "{%0,%1,%2,%3}, {%4,%5,%6,%7}, {%8,%9}, {%0,%1,%2,%3};"
        : "+f"(c[0]), "+f"(c[1]), "+f"(c[2]), "+f"(c[3])
        : "r"(a[0]), "r"(a[1]), "r"(a[2]), "r"(a[3]), "r"(b[0]), "r"(b[1]));
}

// ------------------------------------------- weight transpose+convert -------
// in fp32 [K][N] -> out half [N][K]
__global__ void __launch_bounds__(256) tc_kernel(const float* __restrict__ in,
                                                 __half* __restrict__ out,
                                                 int K, int N) {
    __shared__ float t[32][33];
    const int nb = blockIdx.x * 32, kb = blockIdx.y * 32;
    const int tx = threadIdx.x, ty = threadIdx.y;
    #pragma unroll
    for (int i = 0; i < 32; i += 8)
        t[ty + i][tx] = in[(size_t)(kb + ty + i) * N + nb + tx];
    __syncthreads();
    #pragma unroll
    for (int i = 0; i < 32; i += 8)
        out[(size_t)(nb + ty + i) * K + kb + tx] = __float2half(t[tx][ty + i]);
}

// ---------------------------------------------------------------- LayerNorm --
__global__ void __launch_bounds__(256) ln_kernel(const float* __restrict__ in,
                                                 const float* __restrict__ gamma,
                                                 const float* __restrict__ beta,
                                                 __half* __restrict__ out) {
    const int row = blockIdx.x;
    const float* p = in + (size_t)row * D_MODEL;
    float s = 0.f, sq = 0.f;
    for (int i = threadIdx.x; i < D_MODEL; i += 256) {
        float v = p[i];
        s += v; sq += v * v;
    }
    #pragma unroll
    for (int o = 16; o; o >>= 1) {
        s  += __shfl_xor_sync(0xffffffffu, s,  o);
        sq += __shfl_xor_sync(0xffffffffu, sq, o);
    }
    __shared__ float ws[8], wq[8];
    int w = threadIdx.x >> 5, l = threadIdx.x & 31;
    if (l == 0) { ws[w] = s; wq[w] = sq; }
    __syncthreads();
    if (threadIdx.x == 0) {
        float ts = 0.f, tq = 0.f;
        #pragma unroll
        for (int i = 0; i < 8; i++) { ts += ws[i]; tq += wq[i]; }
        ws[0] = ts; wq[0] = tq;
    }
    __syncthreads();
    const float mu  = ws[0] * (1.f / D_MODEL);
    const float var = wq[0] * (1.f / D_MODEL) - mu * mu;
    const float rs  = rsqrtf(var + 1e-3f);
    __half* po = out + (size_t)row * D_MODEL;
    for (int i = threadIdx.x; i < D_MODEL; i += 256)
        po[i] = __float2half((p[i] - mu) * rs * gamma[i] + beta[i]);
}

// ------------------------------------------------ FP16 mma.sync GEMM --------
// C[M,N] = A[M,K] @ WT[N,K]^T (both half, K-contiguous). CTA 128x128, BK=32,
// 8 warps, warp tile 64x32. smem stride 40 halves (80B, conflict-free).
#define GST 40
#define GS_HALVES (128*GST)
#define GEMM_SMEM_BYTES (4*GS_HALVES*2)   /* A0,A1,B0,B1 = 40960 B */

__device__ __forceinline__ void g_load_stage(const __half* __restrict__ Ag,
                                             const __half* __restrict__ Bg,
                                             int K, uint32_t aBase, uint32_t bBase,
                                             int k0, int tid) {
    #pragma unroll
    for (int p = 0; p < 2; p++) {
        const int id = p * 256 + tid;          // 0..511
        const int r = id >> 2, c8 = (id & 3) * 8;
        cp16(aBase + (r * GST + c8) * 2, Ag + (size_t)r * K + k0 + c8);
        cp16(bBase + (r * GST + c8) * 2, Bg + (size_t)r * K + k0 + c8);
    }
    cp_commit();
}

// EPI 0: bias+relu+QKV scatter ; EPI 1: bias+relu->half ; EPI 2: bias+res->f32
template<int EPI>
__global__ void __launch_bounds__(256, 2) mgemm_kernel(const __half* __restrict__ A,
                                                       const __half* __restrict__ WT,
                                                       const float* __restrict__ bias,
                                                       const float* __restrict__ res,
                                                       void* __restrict__ CoutV,
                                                       int M, int N, int K) {
    extern __shared__ __half hsm[];
    __half* As[2] = { hsm, hsm + GS_HALVES };
    __half* Bs[2] = { hsm + 2 * GS_HALVES, hsm + 3 * GS_HALVES };

    const int tid = threadIdx.x;
    const int wid = tid >> 5, lane = tid & 31;
    const int wm = wid & 1, wn = wid >> 1;
    const int lq = lane >> 2, lr = lane & 3;
    const int bx = blockIdx.x, by = blockIdx.y;

    const __half* Ag = A  + (size_t)(by * 128) * K;
    const __half* Bg = WT + (size_t)(bx * 128) * K;

    const uint32_t aBase[2] = { smem_u32(As[0]), smem_u32(As[1]) };
    const uint32_t bBase[2] = { smem_u32(Bs[0]), smem_u32(Bs[1]) };

    float acc[4][4][4];
    #pragma unroll
    for (int f = 0; f < 4; f++)
        #pragma unroll
        for (int g = 0; g < 4; g++)
            #pragma unroll
            for (int e = 0; e < 4; e++) acc[f][g][e] = 0.f;

    const int iters = K >> 5;
    g_load_stage(Ag, Bg, K, aBase[0], bBase[0], 0, tid);
    g_load_stage(Ag, Bg, K, aBase[1], bBase[1], 32, tid);

    for (int it = 0; it < iters; it++) {
        const int buf = it & 1;
        if (it + 1 < iters) cp_wait1(); else cp_wait0();
        __syncthreads();

        const __half* Asb = As[buf];
        const __half* Bsb = Bs[buf];
        #pragma unroll
        for (int kk = 0; kk < 2; kk++) {
            const int c0 = kk * 16 + lr * 2;
            uint32_t a[4][4], b[4][2];
            #pragma unroll
            for (int f = 0; f < 4; f++) {
                const int r0 = wm * 64 + f * 16 + lq;
                a[f][0] = *(const uint32_t*)&Asb[r0 * GST + c0];
                a[f][1] = *(const uint32_t*)&Asb[(r0 + 8) * GST + c0];
                a[f][2] = *(const uint32_t*)&Asb[r0 * GST + c0 + 8];
                a[f][3] = *(const uint32_t*)&Asb[(r0 + 8) * GST + c0 + 8];
            }
            #pragma unroll
            for (int g = 0; g < 4; g++) {
                const int n0 = wn * 32 + g * 8 + lq;
                b[g][0] = *(const uint32_t*)&Bsb[n0 * GST + c0];
                b[g][1] = *(const uint32_t*)&Bsb[n0 * GST + c0 + 8];
            }
            #pragma unroll
            for (int f = 0; f < 4; f++)
                #pragma unroll
                for (int g = 0; g < 4; g++)
                    mma16(acc[f][g], a[f], b[g]);
        }
        __syncthreads();
        if (it + 2 < iters)
            g_load_stage(Ag, Bg, K, aBase[buf], bBase[buf], (it + 2) << 5, tid);
    }

    #pragma unroll
    for (int f = 0; f < 4; f++) {
        #pragma unroll
        for (int g = 0; g < 4; g++) {
            const int row0 = by * 128 + wm * 64 + f * 16 + lq;
            const int col0 = bx * 128 + wn * 32 + g * 8 + lr * 2;
            #pragma unroll
            for (int h = 0; h < 2; h++) {
                const int row = row0 + h * 8;
                float v0 = acc[f][g][h * 2 + 0] + bias[col0];
                float v1 = acc[f][g][h * 2 + 1] + bias[col0 + 1];
                if (EPI == 0) {
                    v0 = fmaxf(v0, 0.f); v1 = fmaxf(v1, 0.f);
                    #pragma unroll
                    for (int e = 0; e < 2; e++) {
                        const float xv = e ? v1 : v0;
                        const int col = col0 + e;
                        const int cc  = col / 24;
                        const int rem = col - cc * 24;
                        const int hh  = rem / 3;
                        const int ii  = rem - hh * 3;
                        const int bb  = row >> 11;
                        const int nn  = row & 2047;
                        size_t dst;
                        __half* dptr;
                        if (ii == 2) {   // V pre-transposed [b][h][c][n]
                            dptr = g_v;
                            dst = (((size_t)bb * NHEAD + hh) * CHEAD + cc) * SEQ + nn;
                        } else {
                            dptr = (ii == 0) ? g_q : g_k;
                            dst = (((size_t)bb * NHEAD + hh) * SEQ + nn) * CHEAD + cc;
                        }
                        dptr[dst] = __float2half(xv);
                    }
                } else if (EPI == 1) {
                    __half2 o = __floats2half2_rn(fmaxf(v0, 0.f), fmaxf(v1, 0.f));
                    *(__half2*)&((__half*)CoutV)[(size_t)row * N + col0] = o;
                } else {
                    float* Cout = (float*)CoutV;
                    const float2 rr = *(const float2*)&res[(size_t)row * N + col0];
                    float2 o; o.x = v0 + rr.x; o.y = v1 + rr.y;
                    *(float2*)&Cout[(size_t)row * N + col0] = o;
                }
            }
        }
    }
}

// ------------------------------------------------ fp16 tensor Attention -----
// 64 queries/CTA, 256 thr / 8 warps (4x2). No in-kernel transposes.
#define AQ_ST 136   /* sQ, sK row stride (halves) */
#define AV_ST 88    /* sVt row stride (halves)    */
#define AP_ST 72    /* sP row stride (halves)     */
#define AS_ST 68    /* sS row stride (floats)     */
#define ATTN_F32 (64*AS_ST + 192)
#define ATTN_H   (64*AQ_ST + 64*AQ_ST + 128*AV_ST + 64*AP_ST)
#define ATTN_SMEM_BYTES (ATTN_F32*4 + ATTN_H*2)

__global__ void __launch_bounds__(256) attn_kernel(const float* __restrict__ x,
                                                   float* __restrict__ out) {
    extern __shared__ float smf[];
    float* sS = smf;                       // [64][68]
    float* sM = sS + 64 * AS_ST;
    float* sL = sM + 64;
    float* sA = sL + 64;
    __half* sQ  = (__half*)(smf + ATTN_F32);       // [64][136]
    __half* sK  = sQ  + 64 * AQ_ST;                // [64][136]
    __half* sVt = sK  + 64 * AQ_ST;                // [128][88]  ([c][kv])
    __half* sP  = sVt + 128 * AV_ST;               // [64][72]

    const int qb = blockIdx.x, h = blockIdx.y, b = blockIdx.z;
    const int tid = threadIdx.x;
    const int wid = tid >> 5, lane = tid & 31;
    const int lq = lane >> 2, lr = lane & 3;
    const int wm = wid & 3, wn = wid >> 2;   // 4 x 2

    const size_t bh  = ((size_t)b * NHEAD + h) * SEQ;
    const __half* Qg = g_q + (bh + (size_t)qb * 64) * CHEAD;
    const __half* Vb = g_v + ((size_t)b * NHEAD + h) * CHEAD * SEQ;

    for (int idx = tid; idx < 64 * 16; idx += 256) {
        const int r = idx >> 4, c8 = (idx & 15) * 8;
        *(uint4*)&sQ[r * AQ_ST + c8] = *(const uint4*)&Qg[r * 128 + c8];
    }
    if (tid < 64) { sM[tid] = -1e30f; sL[tid] = 0.f; }

    float oacc[8][4];
    #pragma unroll
    for (int f = 0; f < 8; f++)
        #pragma unroll
        for (int e = 0; e < 4; e++) oacc[f][e] = 0.f;

    for (int kt = 0; kt < SEQ / 64; kt++) {
        __syncthreads();
        const __half* Kg = g_k + (bh + (size_t)kt * 64) * CHEAD;
        for (int idx = tid; idx < 64 * 16; idx += 256) {
            const int r = idx >> 4, c8 = (idx & 15) * 8;
            *(uint4*)&sK[r * AQ_ST + c8] = *(const uint4*)&Kg[r * 128 + c8];
        }
        for (int idx = tid; idx < 128 * 8; idx += 256) {
            const int c = idx >> 3, k8 = (idx & 7) * 8;
            *(uint4*)&sVt[c * AV_ST + k8] =
                *(const uint4*)&Vb[(size_t)c * SEQ + kt * 64 + k8];
        }
        __syncthreads();

        // ---- S = Q @ K^T : warp tile 16x32 ---------------------------------
        float sc[4][4];
        #pragma unroll
        for (int g = 0; g < 4; g++)
            #pragma unroll
            for (int e = 0; e < 4; e++) sc[g][e] = 0.f;
        #pragma unroll
        for (int kk = 0; kk < 8; kk++) {
            const int c0 = kk * 16 + lr * 2;
            uint32_t a[4];
            const int r0 = wm * 16 + lq;
            a[0] = *(const uint32_t*)&sQ[r0 * AQ_ST + c0];
            a[1] = *(const uint32_t*)&sQ[(r0 + 8) * AQ_ST + c0];
            a[2] = *(const uint32_t*)&sQ[r0 * AQ_ST + c0 + 8];
            a[3] = *(const uint32_t*)&sQ[(r0 + 8) * AQ_ST + c0 + 8];
            #pragma unroll
            for (int g = 0; g < 4; g++) {
                const int n0 = wn * 32 + g * 8 + lq;
                uint32_t bb[2] = { *(const uint32_t*)&sK[n0 * AQ_ST + c0],
                                   *(const uint32_t*)&sK[n0 * AQ_ST + c0 + 8] };
                mma16(sc[g], a, bb);
            }
        }
        {
            const int r0 = wm * 16 + lq;
            #pragma unroll
            for (int g = 0; g < 4; g++) {
                const int c0 = wn * 32 + g * 8 + lr * 2;
                *(float2*)&sS[r0 * AS_ST + c0] =
                    make_float2(sc[g][0] * 0.125f, sc[g][1] * 0.125f);
                *(float2*)&sS[(r0 + 8) * AS_ST + c0] =
                    make_float2(sc[g][2] * 0.125f, sc[g][3] * 0.125f);
            }
        }
        __syncthreads();

        // ---- online softmax: 4 threads per row -----------------------------
        {
            const int row = tid >> 2, seg = (tid & 3) * 16;
            float* rp = sS + row * AS_ST + seg;
            __half* pp = sP + row * AP_ST + seg;
            float mx = -1e30f;
            #pragma unroll
            for (int j = 0; j < 16; j++) mx = fmaxf(mx, rp[j]);
            mx = fmaxf(mx, __shfl_xor_sync(0xffffffffu, mx, 1));
            mx = fmaxf(mx, __shfl_xor_sync(0xffffffffu, mx, 2));
            const float mo = sM[row];
            const float mn = fmaxf(mo, mx);
            float l = 0.f;
            #pragma unroll
            for (int j = 0; j < 8; j++) {
                const float p0 = __expf(rp[2*j]   - mn);
                const float p1 = __expf(rp[2*j+1] - mn);
                l += p0 + p1;
                *(__half2*)&pp[2*j] = __floats2half2_rn(p0, p1);
            }
            l += __shfl_xor_sync(0xffffffffu, l, 1);
            l += __shfl_xor_sync(0xffffffffu, l, 2);
            if ((tid & 3) == 0) {
                const float alpha = __expf(mo - mn);
                sA[row] = alpha;
                sL[row] = sL[row] * alpha + l;
                sM[row] = mn;
            }
        }
        __syncthreads();

        // ---- O = O*alpha + P @ V : warp tile 16x64 --------------------------
        const float al0 = sA[wm * 16 + lq];
        const float al1 = sA[wm * 16 + lq + 8];
        #pragma unroll
        for (int f = 0; f < 8; f++) {
            oacc[f][0] *= al0; oacc[f][1] *= al0;
            oacc[f][2] *= al1; oacc[f][3] *= al1;
        }
        #pragma unroll
        for (int kk = 0; kk < 4; kk++) {
            const int c0 = kk * 16 + lr * 2;
            uint32_t a[4];
            const int r0 = wm * 16 + lq;
            a[0] = *(const uint32_t*)&sP[r0 * AP_ST + c0];
            a[1] = *(const uint32_t*)&sP[(r0 + 8) * AP_ST + c0];
            a[2] = *(const uint32_t*)&sP[r0 * AP_ST + c0 + 8];
            a[3] = *(const uint32_t*)&sP[(r0 + 8) * AP_ST + c0 + 8];
            #pragma unroll
            for (int f = 0; f < 8; f++) {
                const int n0 = wn * 64 + f * 8 + lq;
                uint32_t bb[2] = { *(const uint32_t*)&sVt[n0 * AV_ST + c0],
                                   *(const uint32_t*)&sVt[n0 * AV_ST + c0 + 8] };
                mma16(oacc[f], a, bb);
            }
        }
    }

    // ------------------------------ epilogue --------------------------------
    const int r0 = wm * 16 + lq;
    const float inv0 = 1.f / sL[r0];
    const float inv1 = 1.f / sL[r0 + 8];
    const int q0 = qb * 64 + r0;
    #pragma unroll
    for (int f = 0; f < 8; f++) {
        const int col = wn * 64 + f * 8 + lr * 2;
        const size_t b0 = ((size_t)b * SEQ + q0) * D_MODEL + h * CHEAD + col;
        const size_t b1 = ((size_t)b * SEQ + q0 + 8) * D_MODEL + h * CHEAD + col;
        const float2 x0 = *(const float2*)&x[b0];
        const float2 x1 = *(const float2*)&x[b1];
        float2 o0, o1;
        o0.x = oacc[f][0] * inv0 + x0.x; o0.y = oacc[f][1] * inv0 + x0.y;
        o1.x = oacc[f][2] * inv1 + x1.x; o1.y = oacc[f][3] * inv1 + x1.y;
        *(float2*)&out[b0] = o0;
        *(float2*)&out[b1] = o1;
    }
}

// ------------------------------------------------------------------ launch --
extern "C" void kernel_launch(void* const* d_in, const int* in_sizes, int n_in,
                              void* d_out, int out_size) {
    const float* x    = (const float*)d_in[0];
    const float* ln_g = (const float*)d_in[1];
    const float* ln_b = (const float*)d_in[2];
    const float* w3   = (const float*)d_in[3];
    const float* b3   = (const float*)d_in[4];
    const float* w1   = (const float*)d_in[5];
    const float* b1   = (const float*)d_in[6];
    const float* w2   = (const float*)d_in[7];
    const float* b2   = (const float*)d_in[8];
    float* out = (float*)d_out;

    __half *yh, *h1, *wh;
    float *att;
    cudaGetSymbolAddress((void**)&yh,  g_yh);
    cudaGetSymbolAddress((void**)&att, g_att);
    cudaGetSymbolAddress((void**)&h1,  g_h1);
    cudaGetSymbolAddress((void**)&wh,  g_wh);

    cudaFuncSetAttribute(attn_kernel, cudaFuncAttributeMaxDynamicSharedMemorySize,
                         ATTN_SMEM_BYTES);
    cudaFuncSetAttribute(mgemm_kernel<0>, cudaFuncAttributeMaxDynamicSharedMemorySize,
                         GEMM_SMEM_BYTES);
    cudaFuncSetAttribute(mgemm_kernel<1>, cudaFuncAttributeMaxDynamicSharedMemorySize,
                         GEMM_SMEM_BYTES);
    cudaFuncSetAttribute(mgemm_kernel<2>, cudaFuncAttributeMaxDynamicSharedMemorySize,
                         GEMM_SMEM_BYTES);

    // 0) weights -> half [N][K]
    tc_kernel<<<dim3(3072/32, 1024/32), dim3(32, 8)>>>(w3, wh + WH3_OFF, 1024, 3072);
    tc_kernel<<<dim3(4096/32, 1024/32), dim3(32, 8)>>>(w1, wh + WH1_OFF, 1024, 4096);
    tc_kernel<<<dim3(1024/32, 4096/32), dim3(32, 8)>>>(w2, wh + WH2_OFF, 4096, 1024);

    // 1) y = LN(x) -> half
    ln_kernel<<<ROWS, 256>>>(x, ln_g, ln_b, yh);
    // 2) qkv = relu(y@w3+b3) -> q/k (n-major), v (c-major)
    mgemm_kernel<0><<<dim3(3072/128, ROWS/128), 256, GEMM_SMEM_BYTES>>>(
        yh, wh + WH3_OFF, b3, nullptr, nullptr, ROWS, 3072, 1024);
    // 3) att = attention(q,k,v) + x   (fp32)
    attn_kernel<<<dim3(SEQ/64, NHEAD, BATCH), 256, ATTN_SMEM_BYTES>>>(x, att);
    // 4) y = LN(att) -> half
    ln_kernel<<<ROWS, 256>>>(att, ln_g, ln_b, yh);
    // 5) h1 = relu(y@w1+b1) -> half
    mgemm_kernel<1><<<dim3(4096/128, ROWS/128), 256, GEMM_SMEM_BYTES>>>(
        yh, wh + WH1_OFF, b1, nullptr, h1, ROWS, 4096, 1024);
    // 6) out = h1@w2 + b2 + att  (fp32)
    mgemm_kernel<2><<<dim3(1024/128, ROWS/128), 256, GEMM_SMEM_BYTES>>>(
        h1, wh + WH2_OFF, b2, att, out, ROWS, 1024, 4096);
}

// round 9
// speedup vs baseline: 5.7437x; 1.1981x over previous
#include <cuda_runtime.h>
#include <cuda_fp16.h>
#include <math.h>
#include <stdint.h>

#define D_MODEL 1024
#define NHEAD 8
#define CHEAD 128
#define BATCH 4
#define SEQ 2048
#define ROWS (BATCH*SEQ)   /* 8192 */

// ---------------- scratch (module-static device memory; no runtime allocs) ---
__device__ __align__(128) __half g_yh [ROWS * D_MODEL];
__device__ __align__(128) __half g_q  [BATCH * NHEAD * SEQ * CHEAD]; // [b][h][n][c]
__device__ __align__(128) __half g_k  [BATCH * NHEAD * SEQ * CHEAD]; // [b][h][n][c]
__device__ __align__(128) __half g_v  [BATCH * NHEAD * CHEAD * SEQ]; // [b][h][c][n]
__device__ __align__(128) float  g_att[ROWS * D_MODEL];
__device__ __align__(128) __half g_h1 [ROWS * 4 * D_MODEL];
#define WH3_OFF 0
#define WH1_OFF (3072*1024)
#define WH2_OFF (WH1_OFF + 4096*1024)
__device__ __align__(128) __half g_wh [WH2_OFF + 1024*4096];

// ------------------------------------------------------------ PTX helpers ---
__device__ __forceinline__ uint32_t smem_u32(const void* p) {
    uint32_t r;
    asm("{ .reg .u64 t; cvta.to.shared.u64 t, %1; cvt.u32.u64 %0, t; }"
        : "=r"(r) : "l"(p));
    return r;
}
__device__ __forceinline__ void cp16(uint32_t dst, const void* src) {
    asm volatile("cp.async.ca.shared.global [%0], [%1], 16;\n" :: "r"(dst), "l"(src));
}
__device__ __forceinline__ void cp_commit() {
    asm volatile("cp.async.commit_group;\n" ::: "memory");
}
__device__ __forceinline__ void cp_wait1() {
    asm volatile("cp.async.wait_group 1;\n" ::: "memory");
}
__device__ __forceinline__ void ldsm4(uint32_t* r, uint32_t addr) {
    asm volatile("ldmatrix.sync.aligned.m8n8.x4.shared.b16 {%0,%1,%2,%3}, [%4];"
        : "=r"(r[0]), "=r"(r[1]), "=r"(r[2]), "=r"(r[3]) : "r"(addr));
}
__device__ __forceinline__ void mma16(float* c, const uint32_t* a, const uint32_t* b) {
    asm volatile(
        "mma.sync.aligned.m16n8k16.row.col.f32.f16.f16.f32 "
        "{%0,%1,%2,%3}, {%4,%5,%6,%7}, {%8,%9}, {%0,%1,%2,%3};"
        : "+f"(c[0]), "+f"(c[1]), "+f"(c[2]), "+f"(c[3])
        : "r"(a[0]), "r"(a[1]), "r"(a[2]), "r"(a[3]), "r"(b[0]), "r"(b[1]));
}

// ------------------------------------------- weight transpose+convert -------
__global__ void __launch_bounds__(256) tc_kernel(const float* __restrict__ in,
                                                 __half* __restrict__ out,
                                                 int K, int N) {
    __shared__ float t[32][33];
    const int nb = blockIdx.x * 32, kb = blockIdx.y * 32;
    const int tx = threadIdx.x, ty = threadIdx.y;
    #pragma unroll
    for (int i = 0; i < 32; i += 8)
        t[ty + i][tx] = in[(size_t)(kb + ty + i) * N + nb + tx];
    __syncthreads();
    #pragma unroll
    for (int i = 0; i < 32; i += 8)
        out[(size_t)(nb + ty + i) * K + kb + tx] = __float2half(t[tx][ty + i]);
}

// ---------------------------------------------------------------- LayerNorm --
__global__ void __launch_bounds__(256) ln_kernel(const float* __restrict__ in,
                                                 const float* __restrict__ gamma,
                                                 const float* __restrict__ beta,
                                                 __half* __restrict__ out) {
    const int row = blockIdx.x;
    const float* p = in + (size_t)row * D_MODEL;
    float s = 0.f, sq = 0.f;
    for (int i = threadIdx.x; i < D_MODEL; i += 256) {
        float v = p[i];
        s += v; sq += v * v;
    }
    #pragma unroll
    for (int o = 16; o; o >>= 1) {
        s  += __shfl_xor_sync(0xffffffffu, s,  o);
        sq += __shfl_xor_sync(0xffffffffu, sq, o);
    }
    __shared__ float ws[8], wq[8];
    int w = threadIdx.x >> 5, l = threadIdx.x & 31;
    if (l == 0) { ws[w] = s; wq[w] = sq; }
    __syncthreads();
    if (threadIdx.x == 0) {
        float ts = 0.f, tq = 0.f;
        #pragma unroll
        for (int i = 0; i < 8; i++) { ts += ws[i]; tq += wq[i]; }
        ws[0] = ts; wq[0] = tq;
    }
    __syncthreads();
    const float mu  = ws[0] * (1.f / D_MODEL);
    const float var = wq[0] * (1.f / D_MODEL) - mu * mu;
    const float rs  = rsqrtf(var + 1e-3f);
    __half* po = out + (size_t)row * D_MODEL;
    for (int i = threadIdx.x; i < D_MODEL; i += 256)
        po[i] = __float2half((p[i] - mu) * rs * gamma[i] + beta[i]);
}

// ------------------------------------------------ FP16 mma.sync GEMM --------
// CTA 128x128, BK=32, 8 warps (2x4), warp tile 64x32. 3-stage cp.async,
// ldmatrix fragment loads, single __syncthreads per mainloop iter.
#define GST 40
#define GS_HALVES (128*GST)
#define GEMM_SMEM_BYTES (6*GS_HALVES*2)   /* 61440 B */

__device__ __forceinline__ void g_load_stage(const __half* __restrict__ Ag,
                                             const __half* __restrict__ Bg,
                                             int K, uint32_t aBase, uint32_t bBase,
                                             int k0, int tid) {
    #pragma unroll
    for (int p = 0; p < 2; p++) {
        const int id = p * 256 + tid;
        const int r = id >> 2, c8 = (id & 3) * 8;
        cp16(aBase + (r * GST + c8) * 2, Ag + (size_t)r * K + k0 + c8);
        cp16(bBase + (r * GST + c8) * 2, Bg + (size_t)r * K + k0 + c8);
    }
    cp_commit();
}

template<int EPI>
__global__ void __launch_bounds__(256, 2) mgemm_kernel(const __half* __restrict__ A,
                                                       const __half* __restrict__ WT,
                                                       const float* __restrict__ bias,
                                                       const float* __restrict__ res,
                                                       void* __restrict__ CoutV,
                                                       int M, int N, int K) {
    extern __shared__ __half hsm[];

    const int tid = threadIdx.x;
    const int wid = tid >> 5, lane = tid & 31;
    const int wm = wid & 1, wn = wid >> 1;
    const int lq = lane >> 2, lr = lane & 3;
    const int bx = blockIdx.x, by = blockIdx.y;

    const __half* Ag = A  + (size_t)(by * 128) * K;
    const __half* Bg = WT + (size_t)(bx * 128) * K;

    uint32_t aBase[3], bBase[3];
    #pragma unroll
    for (int s = 0; s < 3; s++) {
        aBase[s] = smem_u32(hsm + (2 * s)     * GS_HALVES);
        bBase[s] = smem_u32(hsm + (2 * s + 1) * GS_HALVES);
    }

    // ldmatrix per-lane row/k offsets
    const int aRow = lane & 15, aK = (lane >> 4) * 8;                 // A frag
    const int bRow = (lane & 7) + ((lane >> 4) << 3), bK = ((lane >> 3) & 1) * 8;

    float acc[4][4][4];
    #pragma unroll
    for (int f = 0; f < 4; f++)
        #pragma unroll
        for (int g = 0; g < 4; g++)
            #pragma unroll
            for (int e = 0; e < 4; e++) acc[f][g][e] = 0.f;

    const int iters = K >> 5;
    g_load_stage(Ag, Bg, K, aBase[0], bBase[0], 0, tid);
    g_load_stage(Ag, Bg, K, aBase[1], bBase[1], 32, tid);

    int s = 0;
    for (int it = 0; it < iters; it++) {
        cp_wait1();
        __syncthreads();
        if (it + 2 < iters) {
            int ns = s + 2; if (ns >= 3) ns -= 3;          // (it+2)%3 — FIXED
            g_load_stage(Ag, Bg, K, aBase[ns], bBase[ns], (it + 2) << 5, tid);
        }

        #pragma unroll
        for (int kk = 0; kk < 2; kk++) {
            const int c0 = kk * 16;
            uint32_t a[4][4], b[4][2];
            #pragma unroll
            for (int f = 0; f < 4; f++)
                ldsm4(a[f], aBase[s] + ((wm * 64 + f * 16 + aRow) * GST + c0 + aK) * 2);
            #pragma unroll
            for (int g2 = 0; g2 < 2; g2++) {
                uint32_t t4[4];
                ldsm4(t4, bBase[s] + ((wn * 32 + g2 * 16 + bRow) * GST + c0 + bK) * 2);
                b[g2 * 2][0] = t4[0];     b[g2 * 2][1] = t4[1];
                b[g2 * 2 + 1][0] = t4[2]; b[g2 * 2 + 1][1] = t4[3];
            }
            #pragma unroll
            for (int f = 0; f < 4; f++)
                #pragma unroll
                for (int g = 0; g < 4; g++)
                    mma16(acc[f][g], a[f], b[g]);
        }
        s = (s == 2) ? 0 : s + 1;
    }

    #pragma unroll
    for (int f = 0; f < 4; f++) {
        #pragma unroll
        for (int g = 0; g < 4; g++) {
            const int row0 = by * 128 + wm * 64 + f * 16 + lq;
            const int col0 = bx * 128 + wn * 32 + g * 8 + lr * 2;
            #pragma unroll
            for (int h = 0; h < 2; h++) {
                const int row = row0 + h * 8;
                float v0 = acc[f][g][h * 2 + 0] + bias[col0];
                float v1 = acc[f][g][h * 2 + 1] + bias[col0 + 1];
                if (EPI == 0) {
                    v0 = fmaxf(v0, 0.f); v1 = fmaxf(v1, 0.f);
                    #pragma unroll
                    for (int e = 0; e < 2; e++) {
                        const float xv = e ? v1 : v0;
                        const int col = col0 + e;
                        const int cc  = col / 24;
                        const int rem = col - cc * 24;
                        const int hh  = rem / 3;
                        const int ii  = rem - hh * 3;
                        const int bb  = row >> 11;
                        const int nn  = row & 2047;
                        size_t dst;
                        __half* dptr;
                        if (ii == 2) {
                            dptr = g_v;
                            dst = (((size_t)bb * NHEAD + hh) * CHEAD + cc) * SEQ + nn;
                        } else {
                            dptr = (ii == 0) ? g_q : g_k;
                            dst = (((size_t)bb * NHEAD + hh) * SEQ + nn) * CHEAD + cc;
                        }
                        dptr[dst] = __float2half(xv);
                    }
                } else if (EPI == 1) {
                    __half2 o = __floats2half2_rn(fmaxf(v0, 0.f), fmaxf(v1, 0.f));
                    *(__half2*)&((__half*)CoutV)[(size_t)row * N + col0] = o;
                } else {
                    float* Cout = (float*)CoutV;
                    const float2 rr = *(const float2*)&res[(size_t)row * N + col0];
                    float2 o; o.x = v0 + rr.x; o.y = v1 + rr.y;
                    *(float2*)&Cout[(size_t)row * N + col0] = o;
                }
            }
        }
    }
}

// ------------------------------------------------ fp16 tensor Attention -----
#define AQ_ST 136
#define AV_ST 88
#define AP_ST 72
#define AS_ST 68
#define ATTN_F32 (64*AS_ST + 192)
#define ATTN_H   (64*AQ_ST + 64*AQ_ST + 128*AV_ST + 64*AP_ST)
#define ATTN_SMEM_BYTES (ATTN_F32*4 + ATTN_H*2)

__global__ void __launch_bounds__(256) attn_kernel(const float* __restrict__ x,
                                                   float* __restrict__ out) {
    extern __shared__ float smf[];
    float* sS = smf;
    float* sM = sS + 64 * AS_ST;
    float* sL = sM + 64;
    float* sA = sL + 64;
    __half* sQ  = (__half*)(smf + ATTN_F32);
    __half* sK  = sQ  + 64 * AQ_ST;
    __half* sVt = sK  + 64 * AQ_ST;
    __half* sP  = sVt + 128 * AV_ST;

    const int qb = blockIdx.x, h = blockIdx.y, b = blockIdx.z;
    const int tid = threadIdx.x;
    const int wid = tid >> 5, lane = tid & 31;
    const int lq = lane >> 2, lr = lane & 3;
    const int wm = wid & 3, wn = wid >> 2;

    const uint32_t qB  = smem_u32(sQ);
    const uint32_t kB  = smem_u32(sK);
    const uint32_t vB  = smem_u32(sVt);
    const uint32_t pB  = smem_u32(sP);
    const int aRow = lane & 15, aK = (lane >> 4) * 8;
    const int bRow = (lane & 7) + ((lane >> 4) << 3), bK = ((lane >> 3) & 1) * 8;

    const size_t bh  = ((size_t)b * NHEAD + h) * SEQ;
    const __half* Qg = g_q + (bh + (size_t)qb * 64) * CHEAD;
    const __half* Vb = g_v + ((size_t)b * NHEAD + h) * CHEAD * SEQ;

    for (int idx = tid; idx < 64 * 16; idx += 256) {
        const int r = idx >> 4, c8 = (idx & 15) * 8;
        *(uint4*)&sQ[r * AQ_ST + c8] = *(const uint4*)&Qg[r * 128 + c8];
    }
    if (tid < 64) { sM[tid] = -1e30f; sL[tid] = 0.f; }

    float oacc[8][4];
    #pragma unroll
    for (int f = 0; f < 8; f++)
        #pragma unroll
        for (int e = 0; e < 4; e++) oacc[f][e] = 0.f;

    for (int kt = 0; kt < SEQ / 64; kt++) {
        __syncthreads();
        const __half* Kg = g_k + (bh + (size_t)kt * 64) * CHEAD;
        for (int idx = tid; idx < 64 * 16; idx += 256) {
            const int r = idx >> 4, c8 = (idx & 15) * 8;
            *(uint4*)&sK[r * AQ_ST + c8] = *(const uint4*)&Kg[r * 128 + c8];
        }
        for (int idx = tid; idx < 128 * 8; idx += 256) {
            const int c = idx >> 3, k8 = (idx & 7) * 8;
            *(uint4*)&sVt[c * AV_ST + k8] =
                *(const uint4*)&Vb[(size_t)c * SEQ + kt * 64 + k8];
        }
        __syncthreads();

        // ---- S = Q @ K^T ---------------------------------------------------
        float sc[4][4];
        #pragma unroll
        for (int g = 0; g < 4; g++)
            #pragma unroll
            for (int e = 0; e < 4; e++) sc[g][e] = 0.f;
        #pragma unroll
        for (int kk = 0; kk < 8; kk++) {
            const int c0 = kk * 16;
            uint32_t a[4], bfr[4][2];
            ldsm4(a, qB + ((wm * 16 + aRow) * AQ_ST + c0 + aK) * 2);
            #pragma unroll
            for (int g2 = 0; g2 < 2; g2++) {
                uint32_t t4[4];
                ldsm4(t4, kB + ((wn * 32 + g2 * 16 + bRow) * AQ_ST + c0 + bK) * 2);
                bfr[g2 * 2][0] = t4[0];     bfr[g2 * 2][1] = t4[1];
                bfr[g2 * 2 + 1][0] = t4[2]; bfr[g2 * 2 + 1][1] = t4[3];
            }
            #pragma unroll
            for (int g = 0; g < 4; g++)
                mma16(sc[g], a, bfr[g]);
        }
        {
            const int r0 = wm * 16 + lq;
            #pragma unroll
            for (int g = 0; g < 4; g++) {
                const int c0 = wn * 32 + g * 8 + lr * 2;
                *(float2*)&sS[r0 * AS_ST + c0] =
                    make_float2(sc[g][0] * 0.125f, sc[g][1] * 0.125f);
                *(float2*)&sS[(r0 + 8) * AS_ST + c0] =
                    make_float2(sc[g][2] * 0.125f, sc[g][3] * 0.125f);
            }
        }
        __syncthreads();

        // ---- online softmax -------------------------------------------------
        {
            const int row = tid >> 2, seg = (tid & 3) * 16;
            float* rp = sS + row * AS_ST + seg;
            __half* pp = sP + row * AP_ST + seg;
            float mx = -1e30f;
            #pragma unroll
            for (int j = 0; j < 16; j++) mx = fmaxf(mx, rp[j]);
            mx = fmaxf(mx, __shfl_xor_sync(0xffffffffu, mx, 1));
            mx = fmaxf(mx, __shfl_xor_sync(0xffffffffu, mx, 2));
            const float mo = sM[row];
            const float mn = fmaxf(mo, mx);
            float l = 0.f;
            #pragma unroll
            for (int j = 0; j < 8; j++) {
                const float p0 = __expf(rp[2*j]   - mn);
                const float p1 = __expf(rp[2*j+1] - mn);
                l += p0 + p1;
                *(__half2*)&pp[2*j] = __floats2half2_rn(p0, p1);
            }
            l += __shfl_xor_sync(0xffffffffu, l, 1);
            l += __shfl_xor_sync(0xffffffffu, l, 2);
            if ((tid & 3) == 0) {
                const float alpha = __expf(mo - mn);
                sA[row] = alpha;
                sL[row] = sL[row] * alpha + l;
                sM[row] = mn;
            }
        }
        __syncthreads();

        // ---- O = O*alpha + P @ V --------------------------------------------
        const float al0 = sA[wm * 16 + lq];
        const float al1 = sA[wm * 16 + lq + 8];
        #pragma unroll
        for (int f = 0; f < 8; f++) {
            oacc[f][0] *= al0; oacc[f][1] *= al0;
            oacc[f][2] *= al1; oacc[f][3] *= al1;
        }
        #pragma unroll
        for (int kk = 0; kk < 4; kk++) {
            const int c0 = kk * 16;
            uint32_t a[4], bfr[8][2];
            ldsm4(a, pB + ((wm * 16 + aRow) * AP_ST + c0 + aK) * 2);
            #pragma unroll
            for (int f2 = 0; f2 < 4; f2++) {
                uint32_t t4[4];
                ldsm4(t4, vB + ((wn * 64 + f2 * 16 + bRow) * AV_ST + c0 + bK) * 2);
                bfr[f2 * 2][0] = t4[0];     bfr[f2 * 2][1] = t4[1];
                bfr[f2 * 2 + 1][0] = t4[2]; bfr[f2 * 2 + 1][1] = t4[3];
            }
            #pragma unroll
            for (int f = 0; f < 8; f++)
                mma16(oacc[f], a, bfr[f]);
        }
    }

    // ------------------------------ epilogue --------------------------------
    const int r0 = wm * 16 + lq;
    const float inv0 = 1.f / sL[r0];
    const float inv1 = 1.f / sL[r0 + 8];
    const int q0 = qb * 64 + r0;
    #pragma unroll
    for (int f = 0; f < 8; f++) {
        const int col = wn * 64 + f * 8 + lr * 2;
        const size_t b0 = ((size_t)b * SEQ + q0) * D_MODEL + h * CHEAD + col;
        const size_t b1 = ((size_t)b * SEQ + q0 + 8) * D_MODEL + h * CHEAD + col;
        const float2 x0 = *(const float2*)&x[b0];
        const float2 x1 = *(const float2*)&x[b1];
        float2 o0, o1;
        o0.x = oacc[f][0] * inv0 + x0.x; o0.y = oacc[f][1] * inv0 + x0.y;
        o1.x = oacc[f][2] * inv1 + x1.x; o1.y = oacc[f][3] * inv1 + x1.y;
        *(float2*)&out[b0] = o0;
        *(float2*)&out[b1] = o1;
    }
}

// ------------------------------------------------------------------ launch --
extern "C" void kernel_launch(void* const* d_in, const int* in_sizes, int n_in,
                              void* d_out, int out_size) {
    const float* x    = (const float*)d_in[0];
    const float* ln_g = (const float*)d_in[1];
    const float* ln_b = (const float*)d_in[2];
    const float* w3   = (const float*)d_in[3];
    const float* b3   = (const float*)d_in[4];
    const float* w1   = (const float*)d_in[5];
    const float* b1   = (const float*)d_in[6];
    const float* w2   = (const float*)d_in[7];
    const float* b2   = (const float*)d_in[8];
    float* out = (float*)d_out;

    __half *yh, *h1, *wh;
    float *att;
    cudaGetSymbolAddress((void**)&yh,  g_yh);
    cudaGetSymbolAddress((void**)&att, g_att);
    cudaGetSymbolAddress((void**)&h1,  g_h1);
    cudaGetSymbolAddress((void**)&wh,  g_wh);

    cudaFuncSetAttribute(attn_kernel, cudaFuncAttributeMaxDynamicSharedMemorySize,
                         ATTN_SMEM_BYTES);
    cudaFuncSetAttribute(mgemm_kernel<0>, cudaFuncAttributeMaxDynamicSharedMemorySize,
                         GEMM_SMEM_BYTES);
    cudaFuncSetAttribute(mgemm_kernel<1>, cudaFuncAttributeMaxDynamicSharedMemorySize,
                         GEMM_SMEM_BYTES);
    cudaFuncSetAttribute(mgemm_kernel<2>, cudaFuncAttributeMaxDynamicSharedMemorySize,
                         GEMM_SMEM_BYTES);

    tc_kernel<<<dim3(3072/32, 1024/32), dim3(32, 8)>>>(w3, wh + WH3_OFF, 1024, 3072);
    tc_kernel<<<dim3(4096/32, 1024/32), dim3(32, 8)>>>(w1, wh + WH1_OFF, 1024, 4096);
    tc_kernel<<<dim3(1024/32, 4096/32), dim3(32, 8)>>>(w2, wh + WH2_OFF, 4096, 1024);

    ln_kernel<<<ROWS, 256>>>(x, ln_g, ln_b, yh);
    mgemm_kernel<0><<<dim3(3072/128, ROWS/128), 256, GEMM_SMEM_BYTES>>>(
        yh, wh + WH3_OFF, b3, nullptr, nullptr, ROWS, 3072, 1024);
    attn_kernel<<<dim3(SEQ/64, NHEAD, BATCH), 256, ATTN_SMEM_BYTES>>>(x, att);
    ln_kernel<<<ROWS, 256>>>(att, ln_g, ln_b, yh);
    mgemm_kernel<1><<<dim3(4096/128, ROWS/128), 256, GEMM_SMEM_BYTES>>>(
        yh, wh + WH1_OFF, b1, nullptr, h1, ROWS, 4096, 1024);
    mgemm_kernel<2><<<dim3(1024/128, ROWS/128), 256, GEMM_SMEM_BYTES>>>(
        h1, wh + WH2_OFF, b2, att, out, ROWS, 1024, 4096);
}